// round 8
// baseline (speedup 1.0000x reference)
#include <cuda_runtime.h>
#include <mma.h>
#include <cstdint>

using namespace nvcuda;

// Problem constants
#define BQ    4
#define CCH   2
#define SLEN  4096
#define OUTC  512
#define TDIM  72
#define NT    80          // padded t-range per batch (5 x 16)
#define KCH   8           // split-K chunks of 512 k each
#define KTILE 32          // k per smem staging tile
#define SWROW 36

// ---- device scratch (no allocations allowed) ----
__device__ float g_Tpart[KCH * BQ * OUTC * NT];   // [ks][b][o][t80]  5.2 MB
__device__ float g_Tred[BQ * OUTC * TDIM];

// ---- smem layout for mma kernel (float offsets) ----
#define XS_LEN  1104      // raw x window: 2*511 + 79 = 1101, padded
#define A_LDM   36
#define B_LDM   36
#define OFF_XS  0
#define OFF_AHI (OFF_XS + XS_LEN)            // 1104
#define OFF_ALO (OFF_AHI + 128 * A_LDM)      // 1104 + 4608 = 5712
#define OFF_BHI (OFF_ALO + 128 * A_LDM)      // 10320
#define OFF_BLO (OFF_BHI + NT * B_LDM)       // 13200
#define SM_FLOATS (OFF_BLO + NT * B_LDM)     // 16080 floats = 64320 B

// round-to-nearest tf32 (keeps 10 explicit mantissa bits, zeros the rest)
__device__ __forceinline__ float rt32(float w) {
    float r;
    asm("cvt.rna.tf32.f32 %0, %1;" : "=f"(r) : "f"(w));
    return r;
}

// ============================================================================
// Kernel 1: wmma tf32 split-K GEMM partials
//   Tpart[ks][b][o][t] = sum_{k in chunk} conv_w[o, k] * xpad[b, ci, 2q + t]
//   (k = ci*2048 + q;  t < 80, rows beyond window are exact zeros)
// Grid (4 mtile, 4 batch, 8 ks), 256 threads (8 warps).
// Warp w owns rows [mtile*128 + w*16, +16) x all 80 t-cols (5 c-frags).
// Split precision: 3 tf32 products per k-step.
// ============================================================================
__global__ __launch_bounds__(256)
void mma_kernel(const float* __restrict__ x,
                const float* __restrict__ conv_w) {
    extern __shared__ __align__(16) float sm[];
    float* xs  = sm + OFF_XS;
    float* Ahi = sm + OFF_AHI;
    float* Alo = sm + OFF_ALO;
    float* Bhi = sm + OFF_BHI;
    float* Blo = sm + OFF_BLO;

    const int tid = threadIdx.x, wid = tid >> 5;
    const int mtile = blockIdx.x;           // 0..3
    const int b     = blockIdx.y;           // 0..3
    const int ks    = blockIdx.z;           // 0..7
    const int k0    = ks * 512;
    const int ci    = k0 >> 11;             // channel
    const int q0    = k0 & 2047;

    // ---- stage raw x window: xs[j] = xpad[b, ci, 2*q0 + j], j < 1104 ----
    const float* xrow = x + (b * CCH + ci) * SLEN;
    for (int j = tid; j < XS_LEN; j += 256) {
        int g = 2 * q0 + j;
        xs[j] = (g < SLEN) ? xrow[g] : 0.0f;
    }
    __syncthreads();

    wmma::fragment<wmma::accumulator, 16, 16, 8, float> c[5];
    #pragma unroll
    for (int n = 0; n < 5; n++) wmma::fill_fragment(c[n], 0.0f);

    const float* wbase = conv_w + (size_t)(mtile * 128) * 4096 + k0;

    #pragma unroll 1
    for (int tt = 0; tt < 512 / KTILE; tt++) {
        // ---- stage A tile [128 x 32] hi/lo (tf32-rounded) ----
        for (int i = tid; i < 128 * KTILE; i += 256) {
            int r = i >> 5, kk = i & 31;
            float w = __ldg(&wbase[(size_t)r * 4096 + tt * KTILE + kk]);
            float h = rt32(w);
            Ahi[r * A_LDM + kk] = h;
            Alo[r * A_LDM + kk] = rt32(w - h);
        }
        // ---- build B tile [80 x 32] hi/lo from x window ----
        for (int i = tid; i < NT * KTILE; i += 256) {
            int t = i >> 5, kk = i & 31;
            float v = xs[2 * (tt * KTILE + kk) + t];
            float h = rt32(v);
            Bhi[t * B_LDM + kk] = h;
            Blo[t * B_LDM + kk] = rt32(v - h);
        }
        __syncthreads();

        const float* aH = Ahi + wid * 16 * A_LDM;
        const float* aL = Alo + wid * 16 * A_LDM;
        #pragma unroll
        for (int k8 = 0; k8 < KTILE / 8; k8++) {
            wmma::fragment<wmma::matrix_a, 16, 16, 8, wmma::precision::tf32,
                           wmma::row_major> fah, fal;
            wmma::load_matrix_sync(fah, aH + k8 * 8, A_LDM);
            wmma::load_matrix_sync(fal, aL + k8 * 8, A_LDM);
            #pragma unroll
            for (int n = 0; n < 5; n++) {
                wmma::fragment<wmma::matrix_b, 16, 16, 8, wmma::precision::tf32,
                               wmma::col_major> fbh, fbl;
                wmma::load_matrix_sync(fbh, Bhi + n * 16 * B_LDM + k8 * 8, B_LDM);
                wmma::load_matrix_sync(fbl, Blo + n * 16 * B_LDM + k8 * 8, B_LDM);
                wmma::mma_sync(c[n], fah, fbh, c[n]);
                wmma::mma_sync(c[n], fah, fbl, c[n]);
                wmma::mma_sync(c[n], fal, fbh, c[n]);
            }
        }
        __syncthreads();   // done reading tiles before next staging
    }

    // ---- store partials: Tpart[ks][b][o][t80], row-major ldm=80 ----
    float* dst = g_Tpart + (((size_t)ks * BQ + b) * OUTC
                            + mtile * 128 + wid * 16) * NT;
    #pragma unroll
    for (int n = 0; n < 5; n++)
        wmma::store_matrix_sync(dst + n * 16, c[n], NT, wmma::mem_row_major);
}

// ============================================================================
// Kernel 2: split-K reduce + strip t-padding -> g_Tred[(b*512+o)*72 + t]
// ============================================================================
__global__ __launch_bounds__(256)
void reduce_kernel() {
    int i = blockIdx.x * 256 + threadIdx.x;     // over 4*512*72, grid exact
    int bo = i / TDIM, t = i - bo * TDIM;       // bo = b*512 + o
    int b = bo >> 9, o = bo & (OUTC - 1);
    float s = 0.0f;
    #pragma unroll
    for (int ks = 0; ks < KCH; ks++)
        s += g_Tpart[(((size_t)ks * BQ + b) * OUTC + o) * NT + t];
    g_Tred[i] = s;
}

// ============================================================================
// Kernel 3: epilogue (proven layout)
//   out[b,o, p*2048 + m*32 + l] = relu( stft_w[l,m] * T[b,o,p+m] + conv_b[o] )
// ============================================================================
#define BO_PER_BLK 4
__global__ __launch_bounds__(256)
void epilogue_kernel(const float* __restrict__ stft_w,
                     const float* __restrict__ conv_b,
                     float* __restrict__ out) {
    __shared__ __align__(16) float swT[64 * SWROW];
    __shared__ float Ts[BO_PER_BLK * TDIM];
    __shared__ float biasS[BO_PER_BLK];

    const int bo0 = blockIdx.x * BO_PER_BLK;
    const int tid = threadIdx.x;

    for (int i = tid; i < 2048; i += 256) {
        int l = i >> 6, m = i & 63;
        swT[m * SWROW + l] = stft_w[i];
    }
    for (int i = tid; i < BO_PER_BLK * TDIM; i += 256)
        Ts[i] = g_Tred[(size_t)bo0 * TDIM + i];
    if (tid < BO_PER_BLK)
        biasS[tid] = conv_b[(bo0 + tid) & (OUTC - 1)];
    __syncthreads();

    #pragma unroll
    for (int jb = 0; jb < BO_PER_BLK; jb++) {
        const float bias = biasS[jb];
        float4* out4 = (float4*)(out + (size_t)(bo0 + jb) * 4096);
        const float* TsRow = &Ts[jb * TDIM];
        #pragma unroll
        for (int it = 0; it < 4; it++) {
            int q  = tid + it * 256;
            int sp = q * 4;
            int p  = sp >> 11;
            int m  = (sp >> 5) & 63;
            int l0 = sp & 31;
            float tv = TsRow[p + m];
            float4 sw = *(const float4*)&swT[m * SWROW + l0];
            float4 r;
            r.x = fmaxf(fmaf(sw.x, tv, bias), 0.0f);
            r.y = fmaxf(fmaf(sw.y, tv, bias), 0.0f);
            r.z = fmaxf(fmaf(sw.z, tv, bias), 0.0f);
            r.w = fmaxf(fmaf(sw.w, tv, bias), 0.0f);
            out4[q] = r;
        }
    }
}

// ============================================================================
extern "C" void kernel_launch(void* const* d_in, const int* in_sizes, int n_in,
                              void* d_out, int out_size) {
    const float* x      = nullptr;
    const float* stft_w = nullptr;
    const float* conv_w = nullptr;
    const float* conv_b = nullptr;
    for (int i = 0; i < n_in; i++) {
        switch (in_sizes[i]) {
            case BQ * CCH * SLEN:  x      = (const float*)d_in[i]; break;  // 32768
            case 32 * 64:          stft_w = (const float*)d_in[i]; break;  // 2048
            case OUTC * 4096:      conv_w = (const float*)d_in[i]; break;  // 2097152
            case OUTC:             conv_b = (const float*)d_in[i]; break;  // 512
        }
    }

    static int smem_set = 0;
    if (!smem_set) {
        cudaFuncSetAttribute(mma_kernel,
                             cudaFuncAttributeMaxDynamicSharedMemorySize,
                             SM_FLOATS * 4);
        smem_set = 1;
    }

    mma_kernel<<<dim3(4, BQ, KCH), 256, SM_FLOATS * 4>>>(x, conv_w);
    reduce_kernel<<<(BQ * OUTC * TDIM) / 256, 256>>>();
    epilogue_kernel<<<(BQ * OUTC) / BO_PER_BLK, 256>>>(stft_w, conv_b, (float*)d_out);
}

// round 9
// speedup vs baseline: 1.2003x; 1.2003x over previous
#include <cuda_runtime.h>
#include <mma.h>
#include <cstdint>

using namespace nvcuda;

// Problem constants
#define BQ    4
#define CCH   2
#define SLEN  4096
#define OUTC  512
#define TDIM  72
#define NT    80          // padded t-range per batch (5 x 16)
#define KCH   32          // split-K chunks of 128 k each
#define KTILE 32          // k per smem staging tile
#define SWROW 36

// ---- device scratch (no allocations allowed) ----
__device__ float g_Tpart[KCH * BQ * OUTC * NT];   // [ks][b][o][t80]  21 MB
__device__ float g_Tred[BQ * OUTC * TDIM];

// ---- smem layout for mma kernel (float offsets) ----
#define XS_LEN  336       // raw x window: 2*127 + 79 = 333, padded
#define A_LDM   36
#define B_LDM   36
#define OFF_XS  0
#define OFF_AHI (OFF_XS + XS_LEN)            // 336
#define OFF_ALO (OFF_AHI + 128 * A_LDM)      // 336 + 4608
#define OFF_BHI (OFF_ALO + 128 * A_LDM)
#define OFF_BLO (OFF_BHI + NT * B_LDM)
#define SM_FLOATS (OFF_BLO + NT * B_LDM)     // 15312 floats = 61248 B

// round-to-nearest tf32 (keeps 10 explicit mantissa bits, zeros the rest)
__device__ __forceinline__ float rt32(float w) {
    float r;
    asm("cvt.rna.tf32.f32 %0, %1;" : "=f"(r) : "f"(w));
    return r;
}

// ============================================================================
// Kernel 1: wmma tf32 split-K GEMM partials
//   Tpart[ks][b][o][t] = sum_{k in 128-chunk} conv_w[o, k] * xpad[b, ci, 2q + t]
// Grid (4 mtile, 4 batch, 32 ks), 256 threads (8 warps), 3 CTAs/SM.
// Warp w owns rows [mtile*128 + w*16, +16) x all 80 t-cols (5 c-frags).
// Split precision: W = hi+lo, X = hi+lo (tf32); D += Wh*Xh + Wh*Xl + Wl*Xh.
// Products grouped by TYPE across n so each c[n]'s RAW chain has 5
// independent MMAs between dependent ops.
// ============================================================================
__global__ __launch_bounds__(256)
void mma_kernel(const float* __restrict__ x,
                const float* __restrict__ conv_w) {
    extern __shared__ __align__(16) float sm[];
    float* xs  = sm + OFF_XS;
    float* Ahi = sm + OFF_AHI;
    float* Alo = sm + OFF_ALO;
    float* Bhi = sm + OFF_BHI;
    float* Blo = sm + OFF_BLO;

    const int tid = threadIdx.x, wid = tid >> 5;
    const int mtile = blockIdx.x;           // 0..3
    const int b     = blockIdx.y;           // 0..3
    const int ks    = blockIdx.z;           // 0..31
    const int ci    = ks >> 4;              // channel (16 chunks per channel)
    const int q0    = (ks & 15) * 128;

    // ---- stage raw x window: xs[j] = xpad[b, ci, 2*q0 + j], j < 336 ----
    const float* xrow = x + (b * CCH + ci) * SLEN;
    for (int j = tid; j < XS_LEN; j += 256) {
        int g = 2 * q0 + j;
        xs[j] = (g < SLEN) ? xrow[g] : 0.0f;
    }
    __syncthreads();

    wmma::fragment<wmma::accumulator, 16, 16, 8, float> c[5];
    #pragma unroll
    for (int n = 0; n < 5; n++) wmma::fill_fragment(c[n], 0.0f);

    const float* wbase = conv_w + (size_t)(mtile * 128) * 4096 + ks * 128;

    #pragma unroll 1
    for (int tt = 0; tt < 128 / KTILE; tt++) {
        // ---- stage A tile [128 x 32] hi/lo (tf32-rounded) ----
        for (int i = tid; i < 128 * KTILE; i += 256) {
            int r = i >> 5, kk = i & 31;
            float w = __ldg(&wbase[(size_t)r * 4096 + tt * KTILE + kk]);
            float h = rt32(w);
            Ahi[r * A_LDM + kk] = h;
            Alo[r * A_LDM + kk] = rt32(w - h);
        }
        // ---- build B tile [80 x 32] hi/lo from x window ----
        for (int i = tid; i < NT * KTILE; i += 256) {
            int t = i >> 5, kk = i & 31;
            float v = xs[2 * (tt * KTILE + kk) + t];
            float h = rt32(v);
            Bhi[t * B_LDM + kk] = h;
            Blo[t * B_LDM + kk] = rt32(v - h);
        }
        __syncthreads();

        const float* aH = Ahi + wid * 16 * A_LDM;
        const float* aL = Alo + wid * 16 * A_LDM;
        #pragma unroll
        for (int k8 = 0; k8 < KTILE / 8; k8++) {
            wmma::fragment<wmma::matrix_a, 16, 16, 8, wmma::precision::tf32,
                           wmma::row_major> fah, fal;
            wmma::load_matrix_sync(fah, aH + k8 * 8, A_LDM);
            wmma::load_matrix_sync(fal, aL + k8 * 8, A_LDM);
            wmma::fragment<wmma::matrix_b, 16, 16, 8, wmma::precision::tf32,
                           wmma::col_major> fbh[5];
            #pragma unroll
            for (int n = 0; n < 5; n++)
                wmma::load_matrix_sync(fbh[n], Bhi + n * 16 * B_LDM + k8 * 8, B_LDM);
            // product type 1: hi*hi (5 independent)
            #pragma unroll
            for (int n = 0; n < 5; n++) wmma::mma_sync(c[n], fah, fbh[n], c[n]);
            // product type 2: lo*hi (reuses fbh)
            #pragma unroll
            for (int n = 0; n < 5; n++) wmma::mma_sync(c[n], fal, fbh[n], c[n]);
            // product type 3: hi*lo
            #pragma unroll
            for (int n = 0; n < 5; n++) {
                wmma::fragment<wmma::matrix_b, 16, 16, 8, wmma::precision::tf32,
                               wmma::col_major> fbl;
                wmma::load_matrix_sync(fbl, Blo + n * 16 * B_LDM + k8 * 8, B_LDM);
                wmma::mma_sync(c[n], fah, fbl, c[n]);
            }
        }
        __syncthreads();   // done reading tiles before next staging
    }

    // ---- store partials: Tpart[ks][b][o][t80], row-major ldm=80 ----
    float* dst = g_Tpart + (((size_t)ks * BQ + b) * OUTC
                            + mtile * 128 + wid * 16) * NT;
    #pragma unroll
    for (int n = 0; n < 5; n++)
        wmma::store_matrix_sync(dst + n * 16, c[n], NT, wmma::mem_row_major);
}

// ============================================================================
// Kernel 2: split-K reduce + strip t-padding -> g_Tred[(b*512+o)*72 + t]
// ============================================================================
__global__ __launch_bounds__(256)
void reduce_kernel() {
    int i = blockIdx.x * 256 + threadIdx.x;     // over 4*512*72, grid exact
    int bo = i / TDIM, t = i - bo * TDIM;       // bo = b*512 + o
    int b = bo >> 9, o = bo & (OUTC - 1);
    float s = 0.0f;
    #pragma unroll 8
    for (int ks = 0; ks < KCH; ks++)
        s += g_Tpart[(((size_t)ks * BQ + b) * OUTC + o) * NT + t];
    g_Tred[i] = s;
}

// ============================================================================
// Kernel 3: epilogue (proven layout)
//   out[b,o, p*2048 + m*32 + l] = relu( stft_w[l,m] * T[b,o,p+m] + conv_b[o] )
// ============================================================================
#define BO_PER_BLK 4
__global__ __launch_bounds__(256)
void epilogue_kernel(const float* __restrict__ stft_w,
                     const float* __restrict__ conv_b,
                     float* __restrict__ out) {
    __shared__ __align__(16) float swT[64 * SWROW];
    __shared__ float Ts[BO_PER_BLK * TDIM];
    __shared__ float biasS[BO_PER_BLK];

    const int bo0 = blockIdx.x * BO_PER_BLK;
    const int tid = threadIdx.x;

    for (int i = tid; i < 2048; i += 256) {
        int l = i >> 6, m = i & 63;
        swT[m * SWROW + l] = stft_w[i];
    }
    for (int i = tid; i < BO_PER_BLK * TDIM; i += 256)
        Ts[i] = g_Tred[(size_t)bo0 * TDIM + i];
    if (tid < BO_PER_BLK)
        biasS[tid] = conv_b[(bo0 + tid) & (OUTC - 1)];
    __syncthreads();

    #pragma unroll
    for (int jb = 0; jb < BO_PER_BLK; jb++) {
        const float bias = biasS[jb];
        float4* out4 = (float4*)(out + (size_t)(bo0 + jb) * 4096);
        const float* TsRow = &Ts[jb * TDIM];
        #pragma unroll
        for (int it = 0; it < 4; it++) {
            int q  = tid + it * 256;
            int sp = q * 4;
            int p  = sp >> 11;
            int m  = (sp >> 5) & 63;
            int l0 = sp & 31;
            float tv = TsRow[p + m];
            float4 sw = *(const float4*)&swT[m * SWROW + l0];
            float4 r;
            r.x = fmaxf(fmaf(sw.x, tv, bias), 0.0f);
            r.y = fmaxf(fmaf(sw.y, tv, bias), 0.0f);
            r.z = fmaxf(fmaf(sw.z, tv, bias), 0.0f);
            r.w = fmaxf(fmaf(sw.w, tv, bias), 0.0f);
            out4[q] = r;
        }
    }
}

// ============================================================================
extern "C" void kernel_launch(void* const* d_in, const int* in_sizes, int n_in,
                              void* d_out, int out_size) {
    const float* x      = nullptr;
    const float* stft_w = nullptr;
    const float* conv_w = nullptr;
    const float* conv_b = nullptr;
    for (int i = 0; i < n_in; i++) {
        switch (in_sizes[i]) {
            case BQ * CCH * SLEN:  x      = (const float*)d_in[i]; break;  // 32768
            case 32 * 64:          stft_w = (const float*)d_in[i]; break;  // 2048
            case OUTC * 4096:      conv_w = (const float*)d_in[i]; break;  // 2097152
            case OUTC:             conv_b = (const float*)d_in[i]; break;  // 512
        }
    }

    static int smem_set = 0;
    if (!smem_set) {
        cudaFuncSetAttribute(mma_kernel,
                             cudaFuncAttributeMaxDynamicSharedMemorySize,
                             SM_FLOATS * 4);
        smem_set = 1;
    }

    mma_kernel<<<dim3(4, BQ, KCH), 256, SM_FLOATS * 4>>>(x, conv_w);
    reduce_kernel<<<(BQ * OUTC * TDIM) / 256, 256>>>();
    epilogue_kernel<<<(BQ * OUTC) / BO_PER_BLK, 256>>>(stft_w, conv_b, (float*)d_out);
}

// round 10
// speedup vs baseline: 1.3980x; 1.1647x over previous
#include <cuda_runtime.h>
#include <mma.h>
#include <cstdint>

using namespace nvcuda;

// Problem constants
#define BQ    4
#define CCH   2
#define SLEN  4096
#define OUTC  512
#define TDIM  72
#define NT    80          // padded t-range per batch (5 x 16)
#define KCH   32          // split-K chunks of 128 k each
#define KTILE 32          // k per smem staging tile
#define SWROW 36

// ---- device scratch (no allocations allowed) ----
__device__ float g_Tpart[KCH * BQ * OUTC * NT];   // [ks][b][o][t80]  21 MB
__device__ float g_Tred[BQ * OUTC * TDIM];

// ---- smem layout for mma kernel (float offsets) ----
#define XS_LEN  336       // raw x window: 2*127 + 79 = 333, padded
#define A_LDM   36        // 144 B rows (16B aligned)
#define B_LDM   36
#define MROWS   256       // M rows per CTA
#define OFF_XS  0
#define OFF_AHI (OFF_XS + XS_LEN)              // 336
#define OFF_ALO (OFF_AHI + MROWS * A_LDM)      // + 9216
#define OFF_BHI (OFF_ALO + MROWS * A_LDM)      // + 9216
#define OFF_BLO (OFF_BHI + NT * B_LDM)         // + 2880
#define SM_FLOATS (OFF_BLO + NT * B_LDM)       // 24528 floats = 98112 B

// round-to-nearest tf32 (keeps 10 explicit mantissa bits, zeros the rest)
__device__ __forceinline__ float rt32(float w) {
    float r;
    asm("cvt.rna.tf32.f32 %0, %1;" : "=f"(r) : "f"(w));
    return r;
}

// ============================================================================
// Kernel 1: wmma tf32 split-K GEMM partials
//   Tpart[ks][b][o][t] = sum_{k in 128-chunk} conv_w[o, k] * xpad[b, ci, 2q+t]
// Grid (2 mtile, 4 batch, 32 ks) = 256 CTAs, 256 threads (8 warps), 2 CTA/SM.
// CTA: M=256, N=80, K=128. Warp w: rows [mtile*256 + w*32, +32) x 80 cols
// -> c[2][5] accumulators. Per k8-step: 4 A-frag + 10 B-frag loads feed
// 30 wmma (ratio 2.14 MMA/load). Split tf32: Wh*Xh + Wl*Xh + Wh*Xl.
// ============================================================================
__global__ __launch_bounds__(256, 2)
void mma_kernel(const float* __restrict__ x,
                const float* __restrict__ conv_w) {
    extern __shared__ __align__(16) float sm[];
    float* xs  = sm + OFF_XS;
    float* Ahi = sm + OFF_AHI;
    float* Alo = sm + OFF_ALO;
    float* Bhi = sm + OFF_BHI;
    float* Blo = sm + OFF_BLO;

    const int tid = threadIdx.x, wid = tid >> 5;
    const int mtile = blockIdx.x;           // 0..1
    const int b     = blockIdx.y;           // 0..3
    const int ks    = blockIdx.z;           // 0..31
    const int ci    = ks >> 4;              // channel (16 chunks per channel)
    const int q0    = (ks & 15) * 128;

    // ---- stage raw x window: xs[j] = xpad[b, ci, 2*q0 + j], j < 336 ----
    const float* xrow = x + (b * CCH + ci) * SLEN;
    for (int j = tid; j < XS_LEN; j += 256) {
        int g = 2 * q0 + j;
        xs[j] = (g < SLEN) ? xrow[g] : 0.0f;
    }
    __syncthreads();

    wmma::fragment<wmma::accumulator, 16, 16, 8, float> c[2][5];
    #pragma unroll
    for (int i = 0; i < 2; i++)
        #pragma unroll
        for (int n = 0; n < 5; n++) wmma::fill_fragment(c[i][n], 0.0f);

    const float* wbase = conv_w + (size_t)(mtile * MROWS) * 4096 + ks * 128;

    #pragma unroll 1
    for (int tt = 0; tt < 128 / KTILE; tt++) {
        // ---- stage A tile [256 x 32] hi/lo via float4 (tf32-rounded) ----
        for (int i = tid; i < MROWS * (KTILE / 4); i += 256) {
            int r = i >> 3, j4 = (i & 7) * 4;
            float4 w = __ldg((const float4*)(wbase + (size_t)r * 4096
                                             + tt * KTILE + j4));
            float4 h, l;
            h.x = rt32(w.x); l.x = rt32(w.x - h.x);
            h.y = rt32(w.y); l.y = rt32(w.y - h.y);
            h.z = rt32(w.z); l.z = rt32(w.z - h.z);
            h.w = rt32(w.w); l.w = rt32(w.w - h.w);
            *(float4*)&Ahi[r * A_LDM + j4] = h;
            *(float4*)&Alo[r * A_LDM + j4] = l;
        }
        // ---- build B tile [80 x 32] hi/lo from x window ----
        for (int i = tid; i < NT * KTILE; i += 256) {
            int t = i >> 5, kk = i & 31;
            float v = xs[2 * (tt * KTILE + kk) + t];
            float h = rt32(v);
            Bhi[t * B_LDM + kk] = h;
            Blo[t * B_LDM + kk] = rt32(v - h);
        }
        __syncthreads();

        const float* aH = Ahi + (wid * 32) * A_LDM;
        const float* aL = Alo + (wid * 32) * A_LDM;
        #pragma unroll
        for (int k8 = 0; k8 < KTILE / 8; k8++) {
            wmma::fragment<wmma::matrix_a, 16, 16, 8, wmma::precision::tf32,
                           wmma::row_major> fah0, fah1, fal0, fal1;
            wmma::load_matrix_sync(fah0, aH + k8 * 8, A_LDM);
            wmma::load_matrix_sync(fah1, aH + 16 * A_LDM + k8 * 8, A_LDM);
            wmma::load_matrix_sync(fal0, aL + k8 * 8, A_LDM);
            wmma::load_matrix_sync(fal1, aL + 16 * A_LDM + k8 * 8, A_LDM);
            #pragma unroll
            for (int n = 0; n < 5; n++) {
                wmma::fragment<wmma::matrix_b, 16, 16, 8, wmma::precision::tf32,
                               wmma::col_major> fbh, fbl;
                wmma::load_matrix_sync(fbh, Bhi + n * 16 * B_LDM + k8 * 8, B_LDM);
                wmma::load_matrix_sync(fbl, Blo + n * 16 * B_LDM + k8 * 8, B_LDM);
                wmma::mma_sync(c[0][n], fah0, fbh, c[0][n]);
                wmma::mma_sync(c[1][n], fah1, fbh, c[1][n]);
                wmma::mma_sync(c[0][n], fal0, fbh, c[0][n]);
                wmma::mma_sync(c[1][n], fal1, fbh, c[1][n]);
                wmma::mma_sync(c[0][n], fah0, fbl, c[0][n]);
                wmma::mma_sync(c[1][n], fah1, fbl, c[1][n]);
            }
        }
        __syncthreads();   // done reading tiles before next staging
    }

    // ---- store partials: Tpart[ks][b][o][t80], row-major ldm=80 ----
    float* dst = g_Tpart + (((size_t)ks * BQ + b) * OUTC
                            + mtile * MROWS + wid * 32) * NT;
    #pragma unroll
    for (int i = 0; i < 2; i++)
        #pragma unroll
        for (int n = 0; n < 5; n++)
            wmma::store_matrix_sync(dst + i * 16 * NT + n * 16, c[i][n],
                                    NT, wmma::mem_row_major);
}

// ============================================================================
// Kernel 2: split-K reduce + strip t-padding -> g_Tred[(b*512+o)*72 + t]
// ============================================================================
__global__ __launch_bounds__(256)
void reduce_kernel() {
    int i = blockIdx.x * 256 + threadIdx.x;     // over 4*512*72, grid exact
    int bo = i / TDIM, t = i - bo * TDIM;       // bo = b*512 + o
    int b = bo >> 9, o = bo & (OUTC - 1);
    float s = 0.0f;
    #pragma unroll 8
    for (int ks = 0; ks < KCH; ks++)
        s += g_Tpart[(((size_t)ks * BQ + b) * OUTC + o) * NT + t];
    g_Tred[i] = s;
}

// ============================================================================
// Kernel 3: epilogue (proven layout)
//   out[b,o, p*2048 + m*32 + l] = relu( stft_w[l,m] * T[b,o,p+m] + conv_b[o] )
// ============================================================================
#define BO_PER_BLK 4
__global__ __launch_bounds__(256)
void epilogue_kernel(const float* __restrict__ stft_w,
                     const float* __restrict__ conv_b,
                     float* __restrict__ out) {
    __shared__ __align__(16) float swT[64 * SWROW];
    __shared__ float Ts[BO_PER_BLK * TDIM];
    __shared__ float biasS[BO_PER_BLK];

    const int bo0 = blockIdx.x * BO_PER_BLK;
    const int tid = threadIdx.x;

    for (int i = tid; i < 2048; i += 256) {
        int l = i >> 6, m = i & 63;
        swT[m * SWROW + l] = stft_w[i];
    }
    for (int i = tid; i < BO_PER_BLK * TDIM; i += 256)
        Ts[i] = g_Tred[(size_t)bo0 * TDIM + i];
    if (tid < BO_PER_BLK)
        biasS[tid] = conv_b[(bo0 + tid) & (OUTC - 1)];
    __syncthreads();

    #pragma unroll
    for (int jb = 0; jb < BO_PER_BLK; jb++) {
        const float bias = biasS[jb];
        float4* out4 = (float4*)(out + (size_t)(bo0 + jb) * 4096);
        const float* TsRow = &Ts[jb * TDIM];
        #pragma unroll
        for (int it = 0; it < 4; it++) {
            int q  = tid + it * 256;
            int sp = q * 4;
            int p  = sp >> 11;
            int m  = (sp >> 5) & 63;
            int l0 = sp & 31;
            float tv = TsRow[p + m];
            float4 sw = *(const float4*)&swT[m * SWROW + l0];
            float4 r;
            r.x = fmaxf(fmaf(sw.x, tv, bias), 0.0f);
            r.y = fmaxf(fmaf(sw.y, tv, bias), 0.0f);
            r.z = fmaxf(fmaf(sw.z, tv, bias), 0.0f);
            r.w = fmaxf(fmaf(sw.w, tv, bias), 0.0f);
            out4[q] = r;
        }
    }
}

// ============================================================================
extern "C" void kernel_launch(void* const* d_in, const int* in_sizes, int n_in,
                              void* d_out, int out_size) {
    const float* x      = nullptr;
    const float* stft_w = nullptr;
    const float* conv_w = nullptr;
    const float* conv_b = nullptr;
    for (int i = 0; i < n_in; i++) {
        switch (in_sizes[i]) {
            case BQ * CCH * SLEN:  x      = (const float*)d_in[i]; break;  // 32768
            case 32 * 64:          stft_w = (const float*)d_in[i]; break;  // 2048
            case OUTC * 4096:      conv_w = (const float*)d_in[i]; break;  // 2097152
            case OUTC:             conv_b = (const float*)d_in[i]; break;  // 512
        }
    }

    static int smem_set = 0;
    if (!smem_set) {
        cudaFuncSetAttribute(mma_kernel,
                             cudaFuncAttributeMaxDynamicSharedMemorySize,
                             SM_FLOATS * 4);
        smem_set = 1;
    }

    mma_kernel<<<dim3(2, BQ, KCH), 256, SM_FLOATS * 4>>>(x, conv_w);
    reduce_kernel<<<(BQ * OUTC * TDIM) / 256, 256>>>();
    epilogue_kernel<<<(BQ * OUTC) / BO_PER_BLK, 256>>>(stft_w, conv_b, (float*)d_out);
}

// round 11
// speedup vs baseline: 1.4493x; 1.0367x over previous
#include <cuda_runtime.h>
#include <mma.h>
#include <cstdint>

using namespace nvcuda;

// Problem constants
#define BQ    4
#define CCH   2
#define SLEN  4096
#define OUTC  512
#define TDIM  72
#define NT    80          // padded t-range per batch (5 x 16)
#define KCH   32          // split-K chunks of 128 k each
#define KTILE 32          // k per smem staging tile
#define SWROW 36

// ---- device scratch (no allocations allowed) ----
__device__ float g_Tpart[KCH * BQ * OUTC * NT];   // [ks][b][o][t80]  21 MB
__device__ float g_Tred[BQ * OUTC * TDIM];

// ---- smem layout for mma kernel (float offsets) ----
#define XS_LEN  336       // raw x window: 2*127 + 79 = 333, padded
#define A_LDM   36        // 144 B rows (16B aligned)
#define B_LDM   36
#define MROWS   256       // M rows per CTA
#define OFF_XS  0
#define OFF_AHI (OFF_XS + XS_LEN)              // 336
#define OFF_ALO (OFF_AHI + MROWS * A_LDM)      // + 9216
#define OFF_BHI (OFF_ALO + MROWS * A_LDM)      // + 9216
#define OFF_BLO (OFF_BHI + NT * B_LDM)         // + 2880
#define SM_FLOATS (OFF_BLO + NT * B_LDM)       // 24528 floats = 98112 B

// round-to-nearest tf32 (keeps 10 explicit mantissa bits, zeros the rest)
__device__ __forceinline__ float rt32(float w) {
    float r;
    asm("cvt.rna.tf32.f32 %0, %1;" : "=f"(r) : "f"(w));
    return r;
}

// ============================================================================
// Kernel 1: wmma tf32 split-K GEMM partials
//   Tpart[ks][b][o][t] = sum_{k in 128-chunk} conv_w[o, k] * xpad[b, ci, 2q+t]
// Grid (2 mtile, 4 batch, 32 ks) = 256 CTAs, 256 threads (8 warps), 2 CTA/SM.
// CTA: M=256, N=80, K=128. Warp w: rows [w*32, +32) x 80 cols -> c[2][5].
// Inner k8: 3 TYPE-GROUPED passes (hh, lh, hl) with fbh[5] register-cached,
// so every accumulator's RAW chain has distance >= 10 MMAs.
// ============================================================================
__global__ __launch_bounds__(256, 2)
void mma_kernel(const float* __restrict__ x,
                const float* __restrict__ conv_w) {
    extern __shared__ __align__(16) float sm[];
    float* xs  = sm + OFF_XS;
    float* Ahi = sm + OFF_AHI;
    float* Alo = sm + OFF_ALO;
    float* Bhi = sm + OFF_BHI;
    float* Blo = sm + OFF_BLO;

    const int tid = threadIdx.x, wid = tid >> 5;
    const int mtile = blockIdx.x;           // 0..1
    const int b     = blockIdx.y;           // 0..3
    const int ks    = blockIdx.z;           // 0..31
    const int ci    = ks >> 4;              // channel (16 chunks per channel)
    const int q0    = (ks & 15) * 128;

    // ---- stage raw x window: xs[j] = xpad[b, ci, 2*q0 + j], j < 336 ----
    const float* xrow = x + (b * CCH + ci) * SLEN;
    for (int j = tid; j < XS_LEN; j += 256) {
        int g = 2 * q0 + j;
        xs[j] = (g < SLEN) ? xrow[g] : 0.0f;
    }
    __syncthreads();

    wmma::fragment<wmma::accumulator, 16, 16, 8, float> c[2][5];
    #pragma unroll
    for (int i = 0; i < 2; i++)
        #pragma unroll
        for (int n = 0; n < 5; n++) wmma::fill_fragment(c[i][n], 0.0f);

    const float* wbase = conv_w + (size_t)(mtile * MROWS) * 4096 + ks * 128;

    #pragma unroll 1
    for (int tt = 0; tt < 128 / KTILE; tt++) {
        // ---- stage A tile [256 x 32]: batch ALL 8 LDG.128 first (MLP=8) ----
        {
            float4 wv[8];
            #pragma unroll
            for (int j = 0; j < 8; j++) {
                int i = tid + j * 256;
                int r = i >> 3, j4 = (i & 7) * 4;
                wv[j] = __ldg((const float4*)(wbase + (size_t)r * 4096
                                              + tt * KTILE + j4));
            }
            #pragma unroll
            for (int j = 0; j < 8; j++) {
                int i = tid + j * 256;
                int r = i >> 3, j4 = (i & 7) * 4;
                float4 h, l;
                h.x = rt32(wv[j].x); l.x = rt32(wv[j].x - h.x);
                h.y = rt32(wv[j].y); l.y = rt32(wv[j].y - h.y);
                h.z = rt32(wv[j].z); l.z = rt32(wv[j].z - h.z);
                h.w = rt32(wv[j].w); l.w = rt32(wv[j].w - h.w);
                *(float4*)&Ahi[r * A_LDM + j4] = h;
                *(float4*)&Alo[r * A_LDM + j4] = l;
            }
        }
        // ---- build B tile [80 x 32] hi/lo from x window (batched LDS) ----
        {
            float v[10];
            #pragma unroll
            for (int j = 0; j < 10; j++) {
                int i = tid + j * 256;
                int t = i >> 5, kk = i & 31;
                v[j] = xs[2 * (tt * KTILE + kk) + t];
            }
            #pragma unroll
            for (int j = 0; j < 10; j++) {
                int i = tid + j * 256;
                int t = i >> 5, kk = i & 31;
                float h = rt32(v[j]);
                Bhi[t * B_LDM + kk] = h;
                Blo[t * B_LDM + kk] = rt32(v[j] - h);
            }
        }
        __syncthreads();

        const float* aH = Ahi + (wid * 32) * A_LDM;
        const float* aL = Alo + (wid * 32) * A_LDM;
        #pragma unroll
        for (int k8 = 0; k8 < KTILE / 8; k8++) {
            wmma::fragment<wmma::matrix_a, 16, 16, 8, wmma::precision::tf32,
                           wmma::row_major> fah0, fah1;
            wmma::load_matrix_sync(fah0, aH + k8 * 8, A_LDM);
            wmma::load_matrix_sync(fah1, aH + 16 * A_LDM + k8 * 8, A_LDM);
            wmma::fragment<wmma::matrix_b, 16, 16, 8, wmma::precision::tf32,
                           wmma::col_major> fbh[5];
            #pragma unroll
            for (int n = 0; n < 5; n++)
                wmma::load_matrix_sync(fbh[n], Bhi + n * 16 * B_LDM + k8 * 8, B_LDM);

            // pass 1: hi*hi — 10 independent MMAs
            #pragma unroll
            for (int n = 0; n < 5; n++) {
                wmma::mma_sync(c[0][n], fah0, fbh[n], c[0][n]);
                wmma::mma_sync(c[1][n], fah1, fbh[n], c[1][n]);
            }
            // pass 2: lo*hi — reuses fbh
            {
                wmma::fragment<wmma::matrix_a, 16, 16, 8, wmma::precision::tf32,
                               wmma::row_major> fal0, fal1;
                wmma::load_matrix_sync(fal0, aL + k8 * 8, A_LDM);
                wmma::load_matrix_sync(fal1, aL + 16 * A_LDM + k8 * 8, A_LDM);
                #pragma unroll
                for (int n = 0; n < 5; n++) {
                    wmma::mma_sync(c[0][n], fal0, fbh[n], c[0][n]);
                    wmma::mma_sync(c[1][n], fal1, fbh[n], c[1][n]);
                }
            }
            // pass 3: hi*lo — fbl loaded one at a time
            #pragma unroll
            for (int n = 0; n < 5; n++) {
                wmma::fragment<wmma::matrix_b, 16, 16, 8, wmma::precision::tf32,
                               wmma::col_major> fbl;
                wmma::load_matrix_sync(fbl, Blo + n * 16 * B_LDM + k8 * 8, B_LDM);
                wmma::mma_sync(c[0][n], fah0, fbl, c[0][n]);
                wmma::mma_sync(c[1][n], fah1, fbl, c[1][n]);
            }
        }
        __syncthreads();   // done reading tiles before next staging
    }

    // ---- store partials: Tpart[ks][b][o][t80], row-major ldm=80 ----
    float* dst = g_Tpart + (((size_t)ks * BQ + b) * OUTC
                            + mtile * MROWS + wid * 32) * NT;
    #pragma unroll
    for (int i = 0; i < 2; i++)
        #pragma unroll
        for (int n = 0; n < 5; n++)
            wmma::store_matrix_sync(dst + i * 16 * NT + n * 16, c[i][n],
                                    NT, wmma::mem_row_major);
}

// ============================================================================
// Kernel 2: split-K reduce + strip t-padding -> g_Tred[(b*512+o)*72 + t]
// ============================================================================
__global__ __launch_bounds__(256)
void reduce_kernel() {
    int i = blockIdx.x * 256 + threadIdx.x;     // over 4*512*72, grid exact
    int bo = i / TDIM, t = i - bo * TDIM;       // bo = b*512 + o
    int b = bo >> 9, o = bo & (OUTC - 1);
    float s = 0.0f;
    #pragma unroll 8
    for (int ks = 0; ks < KCH; ks++)
        s += g_Tpart[(((size_t)ks * BQ + b) * OUTC + o) * NT + t];
    g_Tred[i] = s;
}

// ============================================================================
// Kernel 3: epilogue (proven layout)
//   out[b,o, p*2048 + m*32 + l] = relu( stft_w[l,m] * T[b,o,p+m] + conv_b[o] )
// ============================================================================
#define BO_PER_BLK 4
__global__ __launch_bounds__(256)
void epilogue_kernel(const float* __restrict__ stft_w,
                     const float* __restrict__ conv_b,
                     float* __restrict__ out) {
    __shared__ __align__(16) float swT[64 * SWROW];
    __shared__ float Ts[BO_PER_BLK * TDIM];
    __shared__ float biasS[BO_PER_BLK];

    const int bo0 = blockIdx.x * BO_PER_BLK;
    const int tid = threadIdx.x;

    for (int i = tid; i < 2048; i += 256) {
        int l = i >> 6, m = i & 63;
        swT[m * SWROW + l] = stft_w[i];
    }
    for (int i = tid; i < BO_PER_BLK * TDIM; i += 256)
        Ts[i] = g_Tred[(size_t)bo0 * TDIM + i];
    if (tid < BO_PER_BLK)
        biasS[tid] = conv_b[(bo0 + tid) & (OUTC - 1)];
    __syncthreads();

    #pragma unroll
    for (int jb = 0; jb < BO_PER_BLK; jb++) {
        const float bias = biasS[jb];
        float4* out4 = (float4*)(out + (size_t)(bo0 + jb) * 4096);
        const float* TsRow = &Ts[jb * TDIM];
        #pragma unroll
        for (int it = 0; it < 4; it++) {
            int q  = tid + it * 256;
            int sp = q * 4;
            int p  = sp >> 11;
            int m  = (sp >> 5) & 63;
            int l0 = sp & 31;
            float tv = TsRow[p + m];
            float4 sw = *(const float4*)&swT[m * SWROW + l0];
            float4 r;
            r.x = fmaxf(fmaf(sw.x, tv, bias), 0.0f);
            r.y = fmaxf(fmaf(sw.y, tv, bias), 0.0f);
            r.z = fmaxf(fmaf(sw.z, tv, bias), 0.0f);
            r.w = fmaxf(fmaf(sw.w, tv, bias), 0.0f);
            out4[q] = r;
        }
    }
}

// ============================================================================
extern "C" void kernel_launch(void* const* d_in, const int* in_sizes, int n_in,
                              void* d_out, int out_size) {
    const float* x      = nullptr;
    const float* stft_w = nullptr;
    const float* conv_w = nullptr;
    const float* conv_b = nullptr;
    for (int i = 0; i < n_in; i++) {
        switch (in_sizes[i]) {
            case BQ * CCH * SLEN:  x      = (const float*)d_in[i]; break;  // 32768
            case 32 * 64:          stft_w = (const float*)d_in[i]; break;  // 2048
            case OUTC * 4096:      conv_w = (const float*)d_in[i]; break;  // 2097152
            case OUTC:             conv_b = (const float*)d_in[i]; break;  // 512
        }
    }

    static int smem_set = 0;
    if (!smem_set) {
        cudaFuncSetAttribute(mma_kernel,
                             cudaFuncAttributeMaxDynamicSharedMemorySize,
                             SM_FLOATS * 4);
        smem_set = 1;
    }

    mma_kernel<<<dim3(2, BQ, KCH), 256, SM_FLOATS * 4>>>(x, conv_w);
    reduce_kernel<<<(BQ * OUTC * TDIM) / 256, 256>>>();
    epilogue_kernel<<<(BQ * OUTC) / BO_PER_BLK, 256>>>(stft_w, conv_b, (float*)d_out);
}

// round 12
// speedup vs baseline: 1.5405x; 1.0629x over previous
#include <cuda_runtime.h>
#include <mma.h>
#include <cstdint>

using namespace nvcuda;

// Problem constants
#define BQ    4
#define CCH   2
#define SLEN  4096
#define OUTC  512
#define TDIM  72
#define NT    80          // padded t-range per batch (5 x 16)
#define KCH   32          // split-K chunks of 128 k each
#define KTILE 16          // k per cp.async staging tile (8 tiles per chunk)
#define NTILES 8
#define SWROW 36

// ---- device scratch (no allocations allowed) ----
__device__ float g_Whi[OUTC * 4096];              // tf32-valued hi part (8 MB)
__device__ float g_Wlo[OUTC * 4096];              // tf32-valued lo part (8 MB)
__device__ float g_Tpart[KCH * BQ * OUTC * NT];   // [ks][b][o][t80]  21 MB
__device__ float g_Tred[BQ * OUTC * TDIM];

// ---- smem layout for mma kernel (float offsets) ----
#define XS_LEN  336       // raw x window: 2*127 + 79 = 333, padded
#define A_LDM   20        // 16 k + 4 pad (80 B rows, 16B aligned)
#define B_LDM   20
#define MROWS   256
#define A_BUF   (MROWS * A_LDM)     // 5120 floats per buffer
#define B_BUF   (NT * B_LDM)        // 1600 floats per buffer
#define OFF_XS  0
#define OFF_AHI (OFF_XS + XS_LEN)              // 336   (2 buffers)
#define OFF_ALO (OFF_AHI + 2 * A_BUF)          // 10576 (2 buffers)
#define OFF_BHI (OFF_ALO + 2 * A_BUF)          // 20816 (2 buffers)
#define SM_FLOATS (OFF_BHI + 2 * B_BUF)        // 24016 floats = 96064 B

// round-to-nearest tf32
__device__ __forceinline__ float rt32(float w) {
    float r;
    asm("cvt.rna.tf32.f32 %0, %1;" : "=f"(r) : "f"(w));
    return r;
}
__device__ __forceinline__ unsigned smem_u32(const void* p) {
    return (unsigned)__cvta_generic_to_shared(p);
}
__device__ __forceinline__ void cp_async16(unsigned dst, const void* src) {
    asm volatile("cp.async.cg.shared.global [%0], [%1], 16;" :: "r"(dst), "l"(src));
}
#define CP_COMMIT()  asm volatile("cp.async.commit_group;")
#define CP_WAIT1()   asm volatile("cp.async.wait_group 1;")

// ============================================================================
// Kernel 0: split conv_w into tf32 hi/lo (both stored as fp32 values)
// ============================================================================
__global__ __launch_bounds__(256)
void wsplit_kernel(const float* __restrict__ w) {
    int i = (blockIdx.x * 256 + threadIdx.x) * 4;   // grid sized exactly
    float4 v = *(const float4*)(w + i);
    float4 h, l;
    h.x = rt32(v.x); l.x = rt32(v.x - h.x);
    h.y = rt32(v.y); l.y = rt32(v.y - h.y);
    h.z = rt32(v.z); l.z = rt32(v.z - h.z);
    h.w = rt32(v.w); l.w = rt32(v.w - h.w);
    *(float4*)(g_Whi + i) = h;
    *(float4*)(g_Wlo + i) = l;
}

// ============================================================================
// Kernel 1: wmma tf32 split-K GEMM partials (2-product split)
//   Tpart[ks][b][o][t] = sum_{k in 128-chunk} conv_w[o,k] * xpad[b,ci,2q+t]
//   D += Wh*Xh + Wl*Xh  ( = W*Xh; dropped W*Xl term ~ 3e-4 rel )
// Grid (2 mtile, 4 batch, 32 ks) = 256 CTAs, 256 thr (8 warps), 2 CTA/SM.
// A tiles (256 x 16 hi/lo) cp.async double-buffered from precomputed
// g_Whi/g_Wlo -> staging latency overlapped with MMA. B built from x window.
// ============================================================================
__global__ __launch_bounds__(256, 2)
void mma_kernel(const float* __restrict__ x) {
    extern __shared__ __align__(16) float sm[];
    float* xs = sm + OFF_XS;

    const int tid = threadIdx.x, wid = tid >> 5;
    const int mtile = blockIdx.x;           // 0..1
    const int b     = blockIdx.y;           // 0..3
    const int ks    = blockIdx.z;           // 0..31
    const int ci    = ks >> 4;
    const int q0    = (ks & 15) * 128;

    const float* srcH = g_Whi + (size_t)(mtile * MROWS) * 4096 + ks * 128;
    const float* srcL = g_Wlo + (size_t)(mtile * MROWS) * 4096 + ks * 128;

    // ---- prologue: cp.async tiles 0 and 1 ----
    #pragma unroll
    for (int pt = 0; pt < 2; pt++) {
        float* AhiB = sm + OFF_AHI + pt * A_BUF;
        float* AloB = sm + OFF_ALO + pt * A_BUF;
        #pragma unroll
        for (int j = 0; j < 4; j++) {
            int i = tid + j * 256;               // 0..1023
            int r = i >> 2, c4 = (i & 3) * 4;
            cp_async16(smem_u32(AhiB + r * A_LDM + c4),
                       srcH + (size_t)r * 4096 + pt * KTILE + c4);
            cp_async16(smem_u32(AloB + r * A_LDM + c4),
                       srcL + (size_t)r * 4096 + pt * KTILE + c4);
        }
        CP_COMMIT();
    }

    // ---- stage raw x window: xs[j] = xpad[b, ci, 2*q0 + j] ----
    const float* xrow = x + (b * CCH + ci) * SLEN;
    for (int j = tid; j < XS_LEN; j += 256) {
        int g = 2 * q0 + j;
        xs[j] = (g < SLEN) ? xrow[g] : 0.0f;
    }
    __syncthreads();   // xs published

    wmma::fragment<wmma::accumulator, 16, 16, 8, float> c[2][5];
    #pragma unroll
    for (int i = 0; i < 2; i++)
        #pragma unroll
        for (int n = 0; n < 5; n++) wmma::fill_fragment(c[i][n], 0.0f);

    #pragma unroll 1
    for (int t = 0; t < NTILES; t++) {
        const int buf = t & 1;
        float* AhiB = sm + OFF_AHI + buf * A_BUF;
        float* AloB = sm + OFF_ALO + buf * A_BUF;
        float* BhiB = sm + OFF_BHI + buf * B_BUF;

        CP_WAIT1();    // tile t's A staging complete (issuing-thread view)

        // build B tile [80 x 16] hi from x window (buffer free since t-2)
        #pragma unroll
        for (int j = 0; j < 5; j++) {
            int i = tid + j * 256;               // 0..1279
            int tt = i >> 4, kk = i & 15;
            BhiB[tt * B_LDM + kk] = rt32(xs[2 * (t * KTILE + kk) + tt]);
        }
        __syncthreads();   // publish A[t] + B[t] block-wide

        const float* aH = AhiB + (wid * 32) * A_LDM;
        const float* aL = AloB + (wid * 32) * A_LDM;
        #pragma unroll
        for (int k8 = 0; k8 < KTILE / 8; k8++) {
            wmma::fragment<wmma::matrix_a, 16, 16, 8, wmma::precision::tf32,
                           wmma::row_major> fah0, fah1;
            wmma::load_matrix_sync(fah0, aH + k8 * 8, A_LDM);
            wmma::load_matrix_sync(fah1, aH + 16 * A_LDM + k8 * 8, A_LDM);
            wmma::fragment<wmma::matrix_b, 16, 16, 8, wmma::precision::tf32,
                           wmma::col_major> fbh[5];
            #pragma unroll
            for (int n = 0; n < 5; n++)
                wmma::load_matrix_sync(fbh[n], BhiB + n * 16 * B_LDM + k8 * 8, B_LDM);

            // pass 1: Wh * Xh — 10 independent MMAs
            #pragma unroll
            for (int n = 0; n < 5; n++) {
                wmma::mma_sync(c[0][n], fah0, fbh[n], c[0][n]);
                wmma::mma_sync(c[1][n], fah1, fbh[n], c[1][n]);
            }
            // pass 2: Wl * Xh — reuses fbh
            {
                wmma::fragment<wmma::matrix_a, 16, 16, 8, wmma::precision::tf32,
                               wmma::row_major> fal0, fal1;
                wmma::load_matrix_sync(fal0, aL + k8 * 8, A_LDM);
                wmma::load_matrix_sync(fal1, aL + 16 * A_LDM + k8 * 8, A_LDM);
                #pragma unroll
                for (int n = 0; n < 5; n++) {
                    wmma::mma_sync(c[0][n], fal0, fbh[n], c[0][n]);
                    wmma::mma_sync(c[1][n], fal1, fbh[n], c[1][n]);
                }
            }
        }
        __syncthreads();   // all warps done with buffer `buf`

        if (t + 2 < NTILES) {
            #pragma unroll
            for (int j = 0; j < 4; j++) {
                int i = tid + j * 256;
                int r = i >> 2, c4 = (i & 3) * 4;
                cp_async16(smem_u32(AhiB + r * A_LDM + c4),
                           srcH + (size_t)r * 4096 + (t + 2) * KTILE + c4);
                cp_async16(smem_u32(AloB + r * A_LDM + c4),
                           srcL + (size_t)r * 4096 + (t + 2) * KTILE + c4);
            }
        }
        CP_COMMIT();   // commit every iteration (keeps wait_group count exact)
    }

    // ---- store partials: Tpart[ks][b][o][t80], row-major ldm=80 ----
    float* dst = g_Tpart + (((size_t)ks * BQ + b) * OUTC
                            + mtile * MROWS + wid * 32) * NT;
    #pragma unroll
    for (int i = 0; i < 2; i++)
        #pragma unroll
        for (int n = 0; n < 5; n++)
            wmma::store_matrix_sync(dst + i * 16 * NT + n * 16, c[i][n],
                                    NT, wmma::mem_row_major);
}

// ============================================================================
// Kernel 2: split-K reduce + strip t-padding -> g_Tred[(b*512+o)*72 + t]
// ============================================================================
__global__ __launch_bounds__(256)
void reduce_kernel() {
    int i = blockIdx.x * 256 + threadIdx.x;     // over 4*512*72, grid exact
    int bo = i / TDIM, t = i - bo * TDIM;       // bo = b*512 + o
    int b = bo >> 9, o = bo & (OUTC - 1);
    float s = 0.0f;
    #pragma unroll 8
    for (int ks = 0; ks < KCH; ks++)
        s += g_Tpart[(((size_t)ks * BQ + b) * OUTC + o) * NT + t];
    g_Tred[i] = s;
}

// ============================================================================
// Kernel 3: epilogue (proven layout)
//   out[b,o, p*2048 + m*32 + l] = relu( stft_w[l,m] * T[b,o,p+m] + conv_b[o] )
// ============================================================================
#define BO_PER_BLK 4
__global__ __launch_bounds__(256)
void epilogue_kernel(const float* __restrict__ stft_w,
                     const float* __restrict__ conv_b,
                     float* __restrict__ out) {
    __shared__ __align__(16) float swT[64 * SWROW];
    __shared__ float Ts[BO_PER_BLK * TDIM];
    __shared__ float biasS[BO_PER_BLK];

    const int bo0 = blockIdx.x * BO_PER_BLK;
    const int tid = threadIdx.x;

    for (int i = tid; i < 2048; i += 256) {
        int l = i >> 6, m = i & 63;
        swT[m * SWROW + l] = stft_w[i];
    }
    for (int i = tid; i < BO_PER_BLK * TDIM; i += 256)
        Ts[i] = g_Tred[(size_t)bo0 * TDIM + i];
    if (tid < BO_PER_BLK)
        biasS[tid] = conv_b[(bo0 + tid) & (OUTC - 1)];
    __syncthreads();

    #pragma unroll
    for (int jb = 0; jb < BO_PER_BLK; jb++) {
        const float bias = biasS[jb];
        float4* out4 = (float4*)(out + (size_t)(bo0 + jb) * 4096);
        const float* TsRow = &Ts[jb * TDIM];
        #pragma unroll
        for (int it = 0; it < 4; it++) {
            int q  = tid + it * 256;
            int sp = q * 4;
            int p  = sp >> 11;
            int m  = (sp >> 5) & 63;
            int l0 = sp & 31;
            float tv = TsRow[p + m];
            float4 sw = *(const float4*)&swT[m * SWROW + l0];
            float4 r;
            r.x = fmaxf(fmaf(sw.x, tv, bias), 0.0f);
            r.y = fmaxf(fmaf(sw.y, tv, bias), 0.0f);
            r.z = fmaxf(fmaf(sw.z, tv, bias), 0.0f);
            r.w = fmaxf(fmaf(sw.w, tv, bias), 0.0f);
            out4[q] = r;
        }
    }
}

// ============================================================================
extern "C" void kernel_launch(void* const* d_in, const int* in_sizes, int n_in,
                              void* d_out, int out_size) {
    const float* x      = nullptr;
    const float* stft_w = nullptr;
    const float* conv_w = nullptr;
    const float* conv_b = nullptr;
    for (int i = 0; i < n_in; i++) {
        switch (in_sizes[i]) {
            case BQ * CCH * SLEN:  x      = (const float*)d_in[i]; break;  // 32768
            case 32 * 64:          stft_w = (const float*)d_in[i]; break;  // 2048
            case OUTC * 4096:      conv_w = (const float*)d_in[i]; break;  // 2097152
            case OUTC:             conv_b = (const float*)d_in[i]; break;  // 512
        }
    }

    static int smem_set = 0;
    if (!smem_set) {
        cudaFuncSetAttribute(mma_kernel,
                             cudaFuncAttributeMaxDynamicSharedMemorySize,
                             SM_FLOATS * 4);
        smem_set = 1;
    }

    wsplit_kernel<<<(OUTC * 4096) / 1024, 256>>>(conv_w);
    mma_kernel<<<dim3(2, BQ, KCH), 256, SM_FLOATS * 4>>>(x);
    reduce_kernel<<<(BQ * OUTC * TDIM) / 256, 256>>>();
    epilogue_kernel<<<(BQ * OUTC) / BO_PER_BLK, 256>>>(stft_w, conv_b, (float*)d_out);
}

// round 13
// speedup vs baseline: 1.6439x; 1.0672x over previous
#include <cuda_runtime.h>
#include <mma.h>
#include <cstdint>

using namespace nvcuda;

// Problem constants
#define BQ    4
#define CCH   2
#define SLEN  4096
#define OUTC  512
#define TDIM  72
#define NT    80          // padded t-range per batch (5 x 16)
#define KCH   32          // split-K chunks of 128 k each
#define KTILE 16          // k per cp.async staging tile
#define NTILES 8
#define SWROW 36

// ---- device scratch (no allocations allowed) ----
__device__ float g_Whi[OUTC * 4096];              // tf32-valued hi part (8 MB)
__device__ float g_Wlo[OUTC * 4096];              // tf32-valued lo part (8 MB)
__device__ float g_Tpart[KCH * BQ * OUTC * NT];   // [ks][b][o][t80]  21 MB
__device__ float g_Tred[BQ * OUTC * TDIM];

// ---- smem layout for mma kernel (float offsets) ----
#define XS_LEN  336       // raw x window: 2*127 + 79 = 333, padded
#define A_LDM   16        // no pad: 64 B rows (cp.async 16B-aligned)
#define B_LDM   20
#define MROWS   256
#define A_BUF   (MROWS * A_LDM)     // 4096 floats per stage per (hi|lo)
#define B_BUF   (NT * B_LDM)        // 1600 floats per buffer
#define NSTAGE  3
#define OFF_XS  0
#define OFF_A   (OFF_XS + XS_LEN)              // 3 stages x (hi, lo)
#define OFF_B   (OFF_A + NSTAGE * 2 * A_BUF)   // 2 buffers
#define SM_FLOATS (OFF_B + 2 * B_BUF)          // 28112 floats = 112448 B

// round-to-nearest tf32
__device__ __forceinline__ float rt32(float w) {
    float r;
    asm("cvt.rna.tf32.f32 %0, %1;" : "=f"(r) : "f"(w));
    return r;
}
__device__ __forceinline__ unsigned smem_u32(const void* p) {
    return (unsigned)__cvta_generic_to_shared(p);
}
__device__ __forceinline__ void cp_async16(unsigned dst, const void* src) {
    asm volatile("cp.async.cg.shared.global [%0], [%1], 16;" :: "r"(dst), "l"(src));
}
#define CP_COMMIT()  asm volatile("cp.async.commit_group;")
#define CP_WAIT1()   asm volatile("cp.async.wait_group 1;")

// ============================================================================
// Kernel 0: split conv_w into tf32 hi/lo (both stored as fp32 values)
// ============================================================================
__global__ __launch_bounds__(256)
void wsplit_kernel(const float* __restrict__ w) {
    int i = (blockIdx.x * 256 + threadIdx.x) * 4;   // grid sized exactly
    float4 v = *(const float4*)(w + i);
    float4 h, l;
    h.x = rt32(v.x); l.x = rt32(v.x - h.x);
    h.y = rt32(v.y); l.y = rt32(v.y - h.y);
    h.z = rt32(v.z); l.z = rt32(v.z - h.z);
    h.w = rt32(v.w); l.w = rt32(v.w - h.w);
    *(float4*)(g_Whi + i) = h;
    *(float4*)(g_Wlo + i) = l;
}

// ============================================================================
// Kernel 1: wmma tf32 split-K GEMM partials (2-product split)
//   Tpart[ks][b][o][t] = sum_{k in 128-chunk} conv_w[o,k] * xpad[b,ci,2q+t]
//   D += Wh*Xh + Wl*Xh
// Grid (2 mtile, 4 batch, 32 ks) = 256 CTAs, 256 thr (8 warps), 2 CTA/SM.
// 3-stage cp.async A pipeline + 2-buffer B rotation; ONE barrier per tile:
//   tile t top-sync publishes A[t] (cp.async) + B[t] (built during t-1) AND
//   proves every warp finished tile t-1's MMAs, so it is safe to (a) issue
//   cp.async A[t+2] into stage (t+2)%3 (= stage of tile t-1) and (b) build
//   B[t+1] into buf (t+1)&1 (= buf of tile t-1). Both overlap tile-t MMAs.
// ============================================================================
__global__ __launch_bounds__(256, 2)
void mma_kernel(const float* __restrict__ x) {
    extern __shared__ __align__(16) float sm[];
    float* xs = sm + OFF_XS;

    const int tid = threadIdx.x, wid = tid >> 5;
    const int mtile = blockIdx.x;           // 0..1
    const int b     = blockIdx.y;           // 0..3
    const int ks    = blockIdx.z;           // 0..31
    const int ci    = ks >> 4;
    const int q0    = (ks & 15) * 128;

    const float* srcH = g_Whi + (size_t)(mtile * MROWS) * 4096 + ks * 128;
    const float* srcL = g_Wlo + (size_t)(mtile * MROWS) * 4096 + ks * 128;

    // ---- prologue: cp.async A stages 0 and 1 ----
    #pragma unroll
    for (int pt = 0; pt < 2; pt++) {
        float* AhiB = sm + OFF_A + (pt * 2    ) * A_BUF;
        float* AloB = sm + OFF_A + (pt * 2 + 1) * A_BUF;
        #pragma unroll
        for (int j = 0; j < 4; j++) {
            int i = tid + j * 256;               // 0..1023
            int r = i >> 2, c4 = (i & 3) * 4;
            cp_async16(smem_u32(AhiB + r * A_LDM + c4),
                       srcH + (size_t)r * 4096 + pt * KTILE + c4);
            cp_async16(smem_u32(AloB + r * A_LDM + c4),
                       srcL + (size_t)r * 4096 + pt * KTILE + c4);
        }
        CP_COMMIT();
    }

    // ---- stage raw x window, then build B[0] ----
    const float* xrow = x + (b * CCH + ci) * SLEN;
    for (int j = tid; j < XS_LEN; j += 256) {
        int g = 2 * q0 + j;
        xs[j] = (g < SLEN) ? xrow[g] : 0.0f;
    }
    __syncthreads();   // xs published
    {
        float* B0 = sm + OFF_B;
        #pragma unroll
        for (int j = 0; j < 5; j++) {
            int i = tid + j * 256;               // 0..1279
            int tt = i >> 4, kk = i & 15;
            B0[tt * B_LDM + kk] = rt32(xs[2 * kk + tt]);
        }
    }

    wmma::fragment<wmma::accumulator, 16, 16, 8, float> c[2][5];
    #pragma unroll
    for (int i = 0; i < 2; i++)
        #pragma unroll
        for (int n = 0; n < 5; n++) wmma::fill_fragment(c[i][n], 0.0f);

    #pragma unroll 1
    for (int t = 0; t < NTILES; t++) {
        const int stg  = t % NSTAGE;
        const int bbuf = t & 1;

        CP_WAIT1();        // A[t] staging complete (issuing-thread view)
        __syncthreads();   // publish A[t] + B[t]; all warps past t-1 MMAs

        // issue A[t+2] into stage (t+2)%3 (tile t-1's stage — safe)
        if (t + 2 < NTILES) {
            const int ns = (t + 2) % NSTAGE;
            float* AhiN = sm + OFF_A + (ns * 2    ) * A_BUF;
            float* AloN = sm + OFF_A + (ns * 2 + 1) * A_BUF;
            #pragma unroll
            for (int j = 0; j < 4; j++) {
                int i = tid + j * 256;
                int r = i >> 2, c4 = (i & 3) * 4;
                cp_async16(smem_u32(AhiN + r * A_LDM + c4),
                           srcH + (size_t)r * 4096 + (t + 2) * KTILE + c4);
                cp_async16(smem_u32(AloN + r * A_LDM + c4),
                           srcL + (size_t)r * 4096 + (t + 2) * KTILE + c4);
            }
        }
        CP_COMMIT();       // commit every iteration (wait_group count exact)

        // build B[t+1] into buf (t+1)&1 (tile t-1's buf — safe)
        if (t + 1 < NTILES) {
            float* Bn = sm + OFF_B + ((t + 1) & 1) * B_BUF;
            #pragma unroll
            for (int j = 0; j < 5; j++) {
                int i = tid + j * 256;
                int tt = i >> 4, kk = i & 15;
                Bn[tt * B_LDM + kk] = rt32(xs[2 * ((t + 1) * KTILE + kk) + tt]);
            }
        }

        // ---- MMAs on tile t ----
        const float* aH = sm + OFF_A + (stg * 2    ) * A_BUF + (wid * 32) * A_LDM;
        const float* aL = sm + OFF_A + (stg * 2 + 1) * A_BUF + (wid * 32) * A_LDM;
        const float* Bt = sm + OFF_B + bbuf * B_BUF;
        #pragma unroll
        for (int k8 = 0; k8 < KTILE / 8; k8++) {
            wmma::fragment<wmma::matrix_a, 16, 16, 8, wmma::precision::tf32,
                           wmma::row_major> fah0, fah1;
            wmma::load_matrix_sync(fah0, aH + k8 * 8, A_LDM);
            wmma::load_matrix_sync(fah1, aH + 16 * A_LDM + k8 * 8, A_LDM);
            wmma::fragment<wmma::matrix_b, 16, 16, 8, wmma::precision::tf32,
                           wmma::col_major> fbh[5];
            #pragma unroll
            for (int n = 0; n < 5; n++)
                wmma::load_matrix_sync(fbh[n], Bt + n * 16 * B_LDM + k8 * 8, B_LDM);

            // pass 1: Wh * Xh — 10 independent MMAs
            #pragma unroll
            for (int n = 0; n < 5; n++) {
                wmma::mma_sync(c[0][n], fah0, fbh[n], c[0][n]);
                wmma::mma_sync(c[1][n], fah1, fbh[n], c[1][n]);
            }
            // pass 2: Wl * Xh — reuses fbh
            {
                wmma::fragment<wmma::matrix_a, 16, 16, 8, wmma::precision::tf32,
                               wmma::row_major> fal0, fal1;
                wmma::load_matrix_sync(fal0, aL + k8 * 8, A_LDM);
                wmma::load_matrix_sync(fal1, aL + 16 * A_LDM + k8 * 8, A_LDM);
                #pragma unroll
                for (int n = 0; n < 5; n++) {
                    wmma::mma_sync(c[0][n], fal0, fbh[n], c[0][n]);
                    wmma::mma_sync(c[1][n], fal1, fbh[n], c[1][n]);
                }
            }
        }
    }

    // ---- store partials: Tpart[ks][b][o][t80], row-major ldm=80 ----
    float* dst = g_Tpart + (((size_t)ks * BQ + b) * OUTC
                            + mtile * MROWS + wid * 32) * NT;
    #pragma unroll
    for (int i = 0; i < 2; i++)
        #pragma unroll
        for (int n = 0; n < 5; n++)
            wmma::store_matrix_sync(dst + i * 16 * NT + n * 16, c[i][n],
                                    NT, wmma::mem_row_major);
}

// ============================================================================
// Kernel 2: split-K reduce + strip t-padding -> g_Tred[(b*512+o)*72 + t]
// ============================================================================
__global__ __launch_bounds__(256)
void reduce_kernel() {
    int i = blockIdx.x * 256 + threadIdx.x;     // over 4*512*72, grid exact
    int bo = i / TDIM, t = i - bo * TDIM;       // bo = b*512 + o
    int b = bo >> 9, o = bo & (OUTC - 1);
    float s = 0.0f;
    #pragma unroll 8
    for (int ks = 0; ks < KCH; ks++)
        s += g_Tpart[(((size_t)ks * BQ + b) * OUTC + o) * NT + t];
    g_Tred[i] = s;
}

// ============================================================================
// Kernel 3: epilogue (2 bo per block -> 1024 blocks for latency hiding)
//   out[b,o, p*2048 + m*32 + l] = relu( stft_w[l,m] * T[b,o,p+m] + conv_b[o] )
// ============================================================================
#define BO_PER_BLK 2
__global__ __launch_bounds__(256)
void epilogue_kernel(const float* __restrict__ stft_w,
                     const float* __restrict__ conv_b,
                     float* __restrict__ out) {
    __shared__ __align__(16) float swT[64 * SWROW];
    __shared__ float Ts[BO_PER_BLK * TDIM];
    __shared__ float biasS[BO_PER_BLK];

    const int bo0 = blockIdx.x * BO_PER_BLK;
    const int tid = threadIdx.x;

    // Ts loads first (longest latency), then swT staging overlaps them
    if (tid < BO_PER_BLK * TDIM)
        Ts[tid] = g_Tred[(size_t)bo0 * TDIM + tid];
    if (tid < BO_PER_BLK)
        biasS[tid] = conv_b[(bo0 + tid) & (OUTC - 1)];
    for (int i = tid; i < 2048; i += 256) {
        int l = i >> 6, m = i & 63;
        swT[m * SWROW + l] = stft_w[i];
    }
    __syncthreads();

    #pragma unroll
    for (int jb = 0; jb < BO_PER_BLK; jb++) {
        const float bias = biasS[jb];
        float4* out4 = (float4*)(out + (size_t)(bo0 + jb) * 4096);
        const float* TsRow = &Ts[jb * TDIM];
        #pragma unroll
        for (int it = 0; it < 4; it++) {
            int q  = tid + it * 256;
            int sp = q * 4;
            int p  = sp >> 11;
            int m  = (sp >> 5) & 63;
            int l0 = sp & 31;
            float tv = TsRow[p + m];
            float4 sw = *(const float4*)&swT[m * SWROW + l0];
            float4 r;
            r.x = fmaxf(fmaf(sw.x, tv, bias), 0.0f);
            r.y = fmaxf(fmaf(sw.y, tv, bias), 0.0f);
            r.z = fmaxf(fmaf(sw.z, tv, bias), 0.0f);
            r.w = fmaxf(fmaf(sw.w, tv, bias), 0.0f);
            out4[q] = r;
        }
    }
}

// ============================================================================
extern "C" void kernel_launch(void* const* d_in, const int* in_sizes, int n_in,
                              void* d_out, int out_size) {
    const float* x      = nullptr;
    const float* stft_w = nullptr;
    const float* conv_w = nullptr;
    const float* conv_b = nullptr;
    for (int i = 0; i < n_in; i++) {
        switch (in_sizes[i]) {
            case BQ * CCH * SLEN:  x      = (const float*)d_in[i]; break;  // 32768
            case 32 * 64:          stft_w = (const float*)d_in[i]; break;  // 2048
            case OUTC * 4096:      conv_w = (const float*)d_in[i]; break;  // 2097152
            case OUTC:             conv_b = (const float*)d_in[i]; break;  // 512
        }
    }

    static int smem_set = 0;
    if (!smem_set) {
        cudaFuncSetAttribute(mma_kernel,
                             cudaFuncAttributeMaxDynamicSharedMemorySize,
                             SM_FLOATS * 4);
        smem_set = 1;
    }

    wsplit_kernel<<<(OUTC * 4096) / 1024, 256>>>(conv_w);
    mma_kernel<<<dim3(2, BQ, KCH), 256, SM_FLOATS * 4>>>(x);
    reduce_kernel<<<(BQ * OUTC * TDIM) / 256, 256>>>();
    epilogue_kernel<<<(BQ * OUTC) / BO_PER_BLK, 256>>>(stft_w, conv_b, (float*)d_out);
}

// round 14
// speedup vs baseline: 1.6988x; 1.0334x over previous
#include <cuda_runtime.h>
#include <mma.h>
#include <cstdint>

using namespace nvcuda;

// Problem constants
#define BQ    4
#define CCH   2
#define SLEN  4096
#define OUTC  512
#define TDIM  72
#define NT    80          // padded t-range per batch (5 x 16)
#define KCH   32          // split-K chunks of 128 k each
#define KTILE 16          // k per cp.async staging tile
#define NTILES 8

// ---- device scratch (no allocations allowed) ----
__device__ float g_Whi[OUTC * 4096];              // tf32-valued hi part (8 MB)
__device__ float g_Wlo[OUTC * 4096];              // tf32-valued lo part (8 MB)
__device__ float g_Tpart[KCH * BQ * OUTC * NT];   // [ks][b][o][t80]  21 MB
__device__ float g_Tred[BQ * OUTC * TDIM];
__device__ float g_swT[2048];                     // transposed stft: [m*32 + l]

// ---- smem layout for mma kernel (float offsets) ----
#define XS_LEN  336       // raw x window: 2*127 + 79 = 333, padded
#define A_LDM   16        // no pad: 64 B rows (cp.async 16B-aligned)
#define B_LDM   20
#define MROWS   256
#define A_BUF   (MROWS * A_LDM)     // 4096 floats per stage per (hi|lo)
#define B_BUF   (NT * B_LDM)        // 1600 floats per buffer
#define NSTAGE  3
#define OFF_XS  0
#define OFF_A   (OFF_XS + XS_LEN)              // 3 stages x (hi, lo)
#define OFF_B   (OFF_A + NSTAGE * 2 * A_BUF)   // 2 buffers
#define SM_FLOATS (OFF_B + 2 * B_BUF)          // 28112 floats = 112448 B

#define RED_BLOCKS ((BQ * OUTC * TDIM) / 256)  // 576

// round-to-nearest tf32
__device__ __forceinline__ float rt32(float w) {
    float r;
    asm("cvt.rna.tf32.f32 %0, %1;" : "=f"(r) : "f"(w));
    return r;
}
__device__ __forceinline__ unsigned smem_u32(const void* p) {
    return (unsigned)__cvta_generic_to_shared(p);
}
__device__ __forceinline__ void cp_async16(unsigned dst, const void* src) {
    asm volatile("cp.async.cg.shared.global [%0], [%1], 16;" :: "r"(dst), "l"(src));
}
#define CP_COMMIT()  asm volatile("cp.async.commit_group;")
#define CP_WAIT1()   asm volatile("cp.async.wait_group 1;")

// ============================================================================
// Kernel 0: split conv_w into tf32 hi/lo (both stored as fp32 values)
// ============================================================================
__global__ __launch_bounds__(256)
void wsplit_kernel(const float* __restrict__ w) {
    int i = (blockIdx.x * 256 + threadIdx.x) * 4;   // grid sized exactly
    float4 v = *(const float4*)(w + i);
    float4 h, l;
    h.x = rt32(v.x); l.x = rt32(v.x - h.x);
    h.y = rt32(v.y); l.y = rt32(v.y - h.y);
    h.z = rt32(v.z); l.z = rt32(v.z - h.z);
    h.w = rt32(v.w); l.w = rt32(v.w - h.w);
    *(float4*)(g_Whi + i) = h;
    *(float4*)(g_Wlo + i) = l;
}

// ============================================================================
// Kernel 1: wmma tf32 split-K GEMM partials (2-product split)  [same as R13]
//   Tpart[ks][b][o][t] = sum_{k in 128-chunk} conv_w[o,k] * xpad[b,ci,2q+t]
//   D += Wh*Xh + Wl*Xh
// Grid (2 mtile, 4 batch, 32 ks) = 256 CTAs, 256 thr (8 warps), 2 CTA/SM.
// 3-stage cp.async A pipeline + 2-buffer B rotation; ONE barrier per tile.
// ============================================================================
__global__ __launch_bounds__(256, 2)
void mma_kernel(const float* __restrict__ x) {
    extern __shared__ __align__(16) float sm[];
    float* xs = sm + OFF_XS;

    const int tid = threadIdx.x, wid = tid >> 5;
    const int mtile = blockIdx.x;           // 0..1
    const int b     = blockIdx.y;           // 0..3
    const int ks    = blockIdx.z;           // 0..31
    const int ci    = ks >> 4;
    const int q0    = (ks & 15) * 128;

    const float* srcH = g_Whi + (size_t)(mtile * MROWS) * 4096 + ks * 128;
    const float* srcL = g_Wlo + (size_t)(mtile * MROWS) * 4096 + ks * 128;

    // ---- prologue: cp.async A stages 0 and 1 ----
    #pragma unroll
    for (int pt = 0; pt < 2; pt++) {
        float* AhiB = sm + OFF_A + (pt * 2    ) * A_BUF;
        float* AloB = sm + OFF_A + (pt * 2 + 1) * A_BUF;
        #pragma unroll
        for (int j = 0; j < 4; j++) {
            int i = tid + j * 256;               // 0..1023
            int r = i >> 2, c4 = (i & 3) * 4;
            cp_async16(smem_u32(AhiB + r * A_LDM + c4),
                       srcH + (size_t)r * 4096 + pt * KTILE + c4);
            cp_async16(smem_u32(AloB + r * A_LDM + c4),
                       srcL + (size_t)r * 4096 + pt * KTILE + c4);
        }
        CP_COMMIT();
    }

    // ---- stage raw x window, then build B[0] ----
    const float* xrow = x + (b * CCH + ci) * SLEN;
    for (int j = tid; j < XS_LEN; j += 256) {
        int g = 2 * q0 + j;
        xs[j] = (g < SLEN) ? xrow[g] : 0.0f;
    }
    __syncthreads();   // xs published
    {
        float* B0 = sm + OFF_B;
        #pragma unroll
        for (int j = 0; j < 5; j++) {
            int i = tid + j * 256;               // 0..1279
            int tt = i >> 4, kk = i & 15;
            B0[tt * B_LDM + kk] = rt32(xs[2 * kk + tt]);
        }
    }

    wmma::fragment<wmma::accumulator, 16, 16, 8, float> c[2][5];
    #pragma unroll
    for (int i = 0; i < 2; i++)
        #pragma unroll
        for (int n = 0; n < 5; n++) wmma::fill_fragment(c[i][n], 0.0f);

    #pragma unroll 1
    for (int t = 0; t < NTILES; t++) {
        const int stg  = t % NSTAGE;
        const int bbuf = t & 1;

        CP_WAIT1();        // A[t] staging complete (issuing-thread view)
        __syncthreads();   // publish A[t] + B[t]; all warps past t-1 MMAs

        // issue A[t+2] into stage (t+2)%3 (tile t-1's stage — safe)
        if (t + 2 < NTILES) {
            const int ns = (t + 2) % NSTAGE;
            float* AhiN = sm + OFF_A + (ns * 2    ) * A_BUF;
            float* AloN = sm + OFF_A + (ns * 2 + 1) * A_BUF;
            #pragma unroll
            for (int j = 0; j < 4; j++) {
                int i = tid + j * 256;
                int r = i >> 2, c4 = (i & 3) * 4;
                cp_async16(smem_u32(AhiN + r * A_LDM + c4),
                           srcH + (size_t)r * 4096 + (t + 2) * KTILE + c4);
                cp_async16(smem_u32(AloN + r * A_LDM + c4),
                           srcL + (size_t)r * 4096 + (t + 2) * KTILE + c4);
            }
        }
        CP_COMMIT();       // commit every iteration (wait_group count exact)

        // build B[t+1] into buf (t+1)&1 (tile t-1's buf — safe)
        if (t + 1 < NTILES) {
            float* Bn = sm + OFF_B + ((t + 1) & 1) * B_BUF;
            #pragma unroll
            for (int j = 0; j < 5; j++) {
                int i = tid + j * 256;
                int tt = i >> 4, kk = i & 15;
                Bn[tt * B_LDM + kk] = rt32(xs[2 * ((t + 1) * KTILE + kk) + tt]);
            }
        }

        // ---- MMAs on tile t ----
        const float* aH = sm + OFF_A + (stg * 2    ) * A_BUF + (wid * 32) * A_LDM;
        const float* aL = sm + OFF_A + (stg * 2 + 1) * A_BUF + (wid * 32) * A_LDM;
        const float* Bt = sm + OFF_B + bbuf * B_BUF;
        #pragma unroll
        for (int k8 = 0; k8 < KTILE / 8; k8++) {
            wmma::fragment<wmma::matrix_a, 16, 16, 8, wmma::precision::tf32,
                           wmma::row_major> fah0, fah1;
            wmma::load_matrix_sync(fah0, aH + k8 * 8, A_LDM);
            wmma::load_matrix_sync(fah1, aH + 16 * A_LDM + k8 * 8, A_LDM);
            wmma::fragment<wmma::matrix_b, 16, 16, 8, wmma::precision::tf32,
                           wmma::col_major> fbh[5];
            #pragma unroll
            for (int n = 0; n < 5; n++)
                wmma::load_matrix_sync(fbh[n], Bt + n * 16 * B_LDM + k8 * 8, B_LDM);

            // pass 1: Wh * Xh — 10 independent MMAs
            #pragma unroll
            for (int n = 0; n < 5; n++) {
                wmma::mma_sync(c[0][n], fah0, fbh[n], c[0][n]);
                wmma::mma_sync(c[1][n], fah1, fbh[n], c[1][n]);
            }
            // pass 2: Wl * Xh — reuses fbh
            {
                wmma::fragment<wmma::matrix_a, 16, 16, 8, wmma::precision::tf32,
                               wmma::row_major> fal0, fal1;
                wmma::load_matrix_sync(fal0, aL + k8 * 8, A_LDM);
                wmma::load_matrix_sync(fal1, aL + 16 * A_LDM + k8 * 8, A_LDM);
                #pragma unroll
                for (int n = 0; n < 5; n++) {
                    wmma::mma_sync(c[0][n], fal0, fbh[n], c[0][n]);
                    wmma::mma_sync(c[1][n], fal1, fbh[n], c[1][n]);
                }
            }
        }
    }

    // ---- store partials: Tpart[ks][b][o][t80], row-major ldm=80 ----
    float* dst = g_Tpart + (((size_t)ks * BQ + b) * OUTC
                            + mtile * MROWS + wid * 32) * NT;
    #pragma unroll
    for (int i = 0; i < 2; i++)
        #pragma unroll
        for (int n = 0; n < 5; n++)
            wmma::store_matrix_sync(dst + i * 16 * NT + n * 16, c[i][n],
                                    NT, wmma::mem_row_major);
}

// ============================================================================
// Kernel 2: split-K reduce -> g_Tred[(b*512+o)*72 + t], PLUS 8 tail blocks
// that build the transposed stft table g_swT[m*32+l] (once, globally).
// ============================================================================
__global__ __launch_bounds__(256)
void reduce_kernel(const float* __restrict__ stft_w) {
    if (blockIdx.x >= RED_BLOCKS) {
        int i = (blockIdx.x - RED_BLOCKS) * 256 + threadIdx.x;   // 0..2047
        int l = i >> 6, m = i & 63;
        g_swT[m * 32 + l] = stft_w[i];
        return;
    }
    int i = blockIdx.x * 256 + threadIdx.x;     // over 4*512*72
    int bo = i / TDIM, t = i - bo * TDIM;       // bo = b*512 + o
    int b = bo >> 9, o = bo & (OUTC - 1);
    float s = 0.0f;
    #pragma unroll 8
    for (int ks = 0; ks < KCH; ks++)
        s += g_Tpart[(((size_t)ks * BQ + b) * OUTC + o) * NT + t];
    g_Tred[i] = s;
}

// ============================================================================
// Kernel 3: epilogue — NO per-block stft staging; sw read straight from
// the shared transposed table g_swT (L2-broadcast), hoisted across jb.
//   out[b,o, p*2048 + m*32 + l] = relu( swT[m,l] * T[b,o,p+m] + conv_b[o] )
// ============================================================================
#define BO_PER_BLK 2
__global__ __launch_bounds__(256)
void epilogue_kernel(const float* __restrict__ conv_b,
                     float* __restrict__ out) {
    __shared__ float Ts[BO_PER_BLK * TDIM];     // 144
    __shared__ float biasS[BO_PER_BLK];

    const int bo0 = blockIdx.x * BO_PER_BLK;
    const int tid = threadIdx.x;

    if (tid < BO_PER_BLK * TDIM)
        Ts[tid] = g_Tred[(size_t)bo0 * TDIM + tid];
    if (tid < BO_PER_BLK)
        biasS[tid] = conv_b[(bo0 + tid) & (OUTC - 1)];

    // hoisted sw loads (identical for both outputs of this block)
    float4 sw[4];
    int   pm[4];
    #pragma unroll
    for (int it = 0; it < 4; it++) {
        int q  = tid + it * 256;      // quad index; s' = 4*q
        int sp = q * 4;
        int p  = sp >> 11;
        int m  = (sp >> 5) & 63;
        int l0 = sp & 31;
        pm[it] = p + m;
        sw[it] = __ldg((const float4*)&g_swT[m * 32 + l0]);
    }
    __syncthreads();

    #pragma unroll
    for (int jb = 0; jb < BO_PER_BLK; jb++) {
        const float bias = biasS[jb];
        float4* out4 = (float4*)(out + (size_t)(bo0 + jb) * 4096);
        const float* TsRow = &Ts[jb * TDIM];
        #pragma unroll
        for (int it = 0; it < 4; it++) {
            float tv = TsRow[pm[it]];
            float4 r;
            r.x = fmaxf(fmaf(sw[it].x, tv, bias), 0.0f);
            r.y = fmaxf(fmaf(sw[it].y, tv, bias), 0.0f);
            r.z = fmaxf(fmaf(sw[it].z, tv, bias), 0.0f);
            r.w = fmaxf(fmaf(sw[it].w, tv, bias), 0.0f);
            out4[tid + it * 256] = r;
        }
    }
}

// ============================================================================
extern "C" void kernel_launch(void* const* d_in, const int* in_sizes, int n_in,
                              void* d_out, int out_size) {
    const float* x      = nullptr;
    const float* stft_w = nullptr;
    const float* conv_w = nullptr;
    const float* conv_b = nullptr;
    for (int i = 0; i < n_in; i++) {
        switch (in_sizes[i]) {
            case BQ * CCH * SLEN:  x      = (const float*)d_in[i]; break;  // 32768
            case 32 * 64:          stft_w = (const float*)d_in[i]; break;  // 2048
            case OUTC * 4096:      conv_w = (const float*)d_in[i]; break;  // 2097152
            case OUTC:             conv_b = (const float*)d_in[i]; break;  // 512
        }
    }

    static int smem_set = 0;
    if (!smem_set) {
        cudaFuncSetAttribute(mma_kernel,
                             cudaFuncAttributeMaxDynamicSharedMemorySize,
                             SM_FLOATS * 4);
        smem_set = 1;
    }

    wsplit_kernel<<<(OUTC * 4096) / 1024, 256>>>(conv_w);
    mma_kernel<<<dim3(2, BQ, KCH), 256, SM_FLOATS * 4>>>(x);
    reduce_kernel<<<RED_BLOCKS + 8, 256>>>(stft_w);
    epilogue_kernel<<<(BQ * OUTC) / BO_PER_BLK, 256>>>(conv_b, (float*)d_out);
}

// round 15
// speedup vs baseline: 2.4236x; 1.4267x over previous
#include <cuda_runtime.h>
#include <mma.h>
#include <cstdint>

using namespace nvcuda;

// Problem constants
#define BQ    4
#define CCH   2
#define SLEN  4096
#define OUTC  512
#define TDIM  72
#define NT    80          // padded t-range per batch (5 x 16)
#define KCH   32          // split-K chunks of 128 k each
#define KTILE 16          // k per cp.async staging tile
#define NTILES 8

// ---- device scratch (no allocations allowed) ----
__device__ float g_Whi[OUTC * 4096];              // tf32-valued weights (8 MB)
__device__ float g_Tpart[KCH * BQ * OUTC * NT];   // [ks][b][o][t80]  21 MB
__device__ float g_Tred[BQ * OUTC * TDIM];
__device__ float g_swT[2048];                     // transposed stft: [m*32 + l]

// ---- smem layout for mma kernel (float offsets) ----
#define XS_LEN  336       // raw x window: 2*127 + 79 = 333, padded
#define A_LDM   16        // no pad: 64 B rows (cp.async 16B-aligned)
#define B_LDM   20
#define MROWS   256
#define A_BUF   (MROWS * A_LDM)     // 4096 floats per stage
#define B_BUF   (NT * B_LDM)        // 1600 floats per buffer
#define NSTAGE  3
#define OFF_XS  0
#define OFF_A   (OFF_XS + XS_LEN)              // 3 stages (hi only)
#define OFF_B   (OFF_A + NSTAGE * A_BUF)       // 2 buffers
#define SM_FLOATS (OFF_B + 2 * B_BUF)          // 15824 floats = 63296 B

#define RED_BLOCKS ((BQ * OUTC * TDIM) / 256)  // 576

// round-to-nearest tf32
__device__ __forceinline__ float rt32(float w) {
    float r;
    asm("cvt.rna.tf32.f32 %0, %1;" : "=f"(r) : "f"(w));
    return r;
}
__device__ __forceinline__ unsigned smem_u32(const void* p) {
    return (unsigned)__cvta_generic_to_shared(p);
}
__device__ __forceinline__ void cp_async16(unsigned dst, const void* src) {
    asm volatile("cp.async.cg.shared.global [%0], [%1], 16;" :: "r"(dst), "l"(src));
}
#define CP_COMMIT()  asm volatile("cp.async.commit_group;")
#define CP_WAIT1()   asm volatile("cp.async.wait_group 1;")

// ============================================================================
// Kernel 0: round conv_w to tf32 values (hi part only — single-product mode)
// ============================================================================
__global__ __launch_bounds__(256)
void wsplit_kernel(const float* __restrict__ w) {
    int i = (blockIdx.x * 256 + threadIdx.x) * 4;   // grid sized exactly
    float4 v = *(const float4*)(w + i);
    float4 h;
    h.x = rt32(v.x); h.y = rt32(v.y); h.z = rt32(v.z); h.w = rt32(v.w);
    *(float4*)(g_Whi + i) = h;
}

// ============================================================================
// Kernel 1: wmma tf32 split-K GEMM partials (single product: D = Wh * Xh)
//   Tpart[ks][b][o][t] = sum_{k in 128-chunk} Wh[o,k] * Xh[b,ci,2q+t]
// Grid (2 mtile, 4 batch, 32 ks) = 256 CTAs, 256 thr (8 warps), 2 CTA/SM.
// 3-stage cp.async A pipeline + 2-buffer B rotation; ONE barrier per tile:
//   tile t top-sync publishes A[t] (cp.async) + B[t] (built during t-1) AND
//   proves all warps finished tile t-1's MMAs -> safe to (a) issue cp.async
//   A[t+2] into stage (t+2)%3 (t-1's stage) and (b) build B[t+1] into buf
//   (t+1)&1 (t-1's buf). Both overlap tile-t MMAs.
// ============================================================================
__global__ __launch_bounds__(256, 2)
void mma_kernel(const float* __restrict__ x) {
    extern __shared__ __align__(16) float sm[];
    float* xs = sm + OFF_XS;

    const int tid = threadIdx.x, wid = tid >> 5;
    const int mtile = blockIdx.x;           // 0..1
    const int b     = blockIdx.y;           // 0..3
    const int ks    = blockIdx.z;           // 0..31
    const int ci    = ks >> 4;
    const int q0    = (ks & 15) * 128;

    const float* srcH = g_Whi + (size_t)(mtile * MROWS) * 4096 + ks * 128;

    // ---- prologue: cp.async A stages 0 and 1 ----
    #pragma unroll
    for (int pt = 0; pt < 2; pt++) {
        float* AB = sm + OFF_A + pt * A_BUF;
        #pragma unroll
        for (int j = 0; j < 4; j++) {
            int i = tid + j * 256;               // 0..1023
            int r = i >> 2, c4 = (i & 3) * 4;
            cp_async16(smem_u32(AB + r * A_LDM + c4),
                       srcH + (size_t)r * 4096 + pt * KTILE + c4);
        }
        CP_COMMIT();
    }

    // ---- stage raw x window, then build B[0] ----
    const float* xrow = x + (b * CCH + ci) * SLEN;
    for (int j = tid; j < XS_LEN; j += 256) {
        int g = 2 * q0 + j;
        xs[j] = (g < SLEN) ? xrow[g] : 0.0f;
    }
    __syncthreads();   // xs published
    {
        float* B0 = sm + OFF_B;
        #pragma unroll
        for (int j = 0; j < 5; j++) {
            int i = tid + j * 256;               // 0..1279
            int tt = i >> 4, kk = i & 15;
            B0[tt * B_LDM + kk] = rt32(xs[2 * kk + tt]);
        }
    }

    wmma::fragment<wmma::accumulator, 16, 16, 8, float> c[2][5];
    #pragma unroll
    for (int i = 0; i < 2; i++)
        #pragma unroll
        for (int n = 0; n < 5; n++) wmma::fill_fragment(c[i][n], 0.0f);

    #pragma unroll 1
    for (int t = 0; t < NTILES; t++) {
        const int stg  = t % NSTAGE;
        const int bbuf = t & 1;

        CP_WAIT1();        // A[t] staging complete (issuing-thread view)
        __syncthreads();   // publish A[t] + B[t]; all warps past t-1 MMAs

        // issue A[t+2] into stage (t+2)%3 (tile t-1's stage — safe)
        if (t + 2 < NTILES) {
            float* AN = sm + OFF_A + ((t + 2) % NSTAGE) * A_BUF;
            #pragma unroll
            for (int j = 0; j < 4; j++) {
                int i = tid + j * 256;
                int r = i >> 2, c4 = (i & 3) * 4;
                cp_async16(smem_u32(AN + r * A_LDM + c4),
                           srcH + (size_t)r * 4096 + (t + 2) * KTILE + c4);
            }
        }
        CP_COMMIT();       // commit every iteration (wait_group count exact)

        // build B[t+1] into buf (t+1)&1 (tile t-1's buf — safe)
        if (t + 1 < NTILES) {
            float* Bn = sm + OFF_B + ((t + 1) & 1) * B_BUF;
            #pragma unroll
            for (int j = 0; j < 5; j++) {
                int i = tid + j * 256;
                int tt = i >> 4, kk = i & 15;
                Bn[tt * B_LDM + kk] = rt32(xs[2 * ((t + 1) * KTILE + kk) + tt]);
            }
        }

        // ---- MMAs on tile t: D += Wh * Xh ----
        const float* aH = sm + OFF_A + stg * A_BUF + (wid * 32) * A_LDM;
        const float* Bt = sm + OFF_B + bbuf * B_BUF;
        #pragma unroll
        for (int k8 = 0; k8 < KTILE / 8; k8++) {
            wmma::fragment<wmma::matrix_a, 16, 16, 8, wmma::precision::tf32,
                           wmma::row_major> fah0, fah1;
            wmma::load_matrix_sync(fah0, aH + k8 * 8, A_LDM);
            wmma::load_matrix_sync(fah1, aH + 16 * A_LDM + k8 * 8, A_LDM);
            #pragma unroll
            for (int n = 0; n < 5; n++) {
                wmma::fragment<wmma::matrix_b, 16, 16, 8, wmma::precision::tf32,
                               wmma::col_major> fbh;
                wmma::load_matrix_sync(fbh, Bt + n * 16 * B_LDM + k8 * 8, B_LDM);
                wmma::mma_sync(c[0][n], fah0, fbh, c[0][n]);
                wmma::mma_sync(c[1][n], fah1, fbh, c[1][n]);
            }
        }
    }

    // ---- store partials: Tpart[ks][b][o][t80], row-major ldm=80 ----
    float* dst = g_Tpart + (((size_t)ks * BQ + b) * OUTC
                            + mtile * MROWS + wid * 32) * NT;
    #pragma unroll
    for (int i = 0; i < 2; i++)
        #pragma unroll
        for (int n = 0; n < 5; n++)
            wmma::store_matrix_sync(dst + i * 16 * NT + n * 16, c[i][n],
                                    NT, wmma::mem_row_major);
}

// ============================================================================
// Kernel 2: split-K reduce -> g_Tred[(b*512+o)*72 + t], PLUS 8 tail blocks
// that build the transposed stft table g_swT[m*32+l] (once, globally).
// ============================================================================
__global__ __launch_bounds__(256)
void reduce_kernel(const float* __restrict__ stft_w) {
    if (blockIdx.x >= RED_BLOCKS) {
        int i = (blockIdx.x - RED_BLOCKS) * 256 + threadIdx.x;   // 0..2047
        int l = i >> 6, m = i & 63;
        g_swT[m * 32 + l] = stft_w[i];
        return;
    }
    int i = blockIdx.x * 256 + threadIdx.x;     // over 4*512*72
    int bo = i / TDIM, t = i - bo * TDIM;       // bo = b*512 + o
    int b = bo >> 9, o = bo & (OUTC - 1);
    float s = 0.0f;
    #pragma unroll 8
    for (int ks = 0; ks < KCH; ks++)
        s += g_Tpart[(((size_t)ks * BQ + b) * OUTC + o) * NT + t];
    g_Tred[i] = s;
}

// ============================================================================
// Kernel 3: epilogue — sw loads (L2-broadcast from g_swT) hoisted and
// amortized over 4 outputs per block.
//   out[b,o, p*2048 + m*32 + l] = relu( swT[m,l] * T[b,o,p+m] + conv_b[o] )
// ============================================================================
#define BO_PER_BLK 4
__global__ __launch_bounds__(256)
void epilogue_kernel(const float* __restrict__ conv_b,
                     float* __restrict__ out) {
    __shared__ float Ts[BO_PER_BLK * TDIM];     // 288
    __shared__ float biasS[BO_PER_BLK];

    const int bo0 = blockIdx.x * BO_PER_BLK;
    const int tid = threadIdx.x;

    for (int i = tid; i < BO_PER_BLK * TDIM; i += 256)
        Ts[i] = g_Tred[(size_t)bo0 * TDIM + i];
    if (tid < BO_PER_BLK)
        biasS[tid] = conv_b[(bo0 + tid) & (OUTC - 1)];

    // hoisted sw loads (identical for all 4 outputs of this block)
    float4 sw[4];
    int   pm[4];
    #pragma unroll
    for (int it = 0; it < 4; it++) {
        int q  = tid + it * 256;      // quad index; s' = 4*q
        int sp = q * 4;
        int p  = sp >> 11;
        int m  = (sp >> 5) & 63;
        int l0 = sp & 31;
        pm[it] = p + m;
        sw[it] = __ldg((const float4*)&g_swT[m * 32 + l0]);
    }
    __syncthreads();

    #pragma unroll
    for (int jb = 0; jb < BO_PER_BLK; jb++) {
        const float bias = biasS[jb];
        float4* out4 = (float4*)(out + (size_t)(bo0 + jb) * 4096);
        const float* TsRow = &Ts[jb * TDIM];
        #pragma unroll
        for (int it = 0; it < 4; it++) {
            float tv = TsRow[pm[it]];
            float4 r;
            r.x = fmaxf(fmaf(sw[it].x, tv, bias), 0.0f);
            r.y = fmaxf(fmaf(sw[it].y, tv, bias), 0.0f);
            r.z = fmaxf(fmaf(sw[it].z, tv, bias), 0.0f);
            r.w = fmaxf(fmaf(sw[it].w, tv, bias), 0.0f);
            out4[tid + it * 256] = r;
        }
    }
}

// ============================================================================
extern "C" void kernel_launch(void* const* d_in, const int* in_sizes, int n_in,
                              void* d_out, int out_size) {
    const float* x      = nullptr;
    const float* stft_w = nullptr;
    const float* conv_w = nullptr;
    const float* conv_b = nullptr;
    for (int i = 0; i < n_in; i++) {
        switch (in_sizes[i]) {
            case BQ * CCH * SLEN:  x      = (const float*)d_in[i]; break;  // 32768
            case 32 * 64:          stft_w = (const float*)d_in[i]; break;  // 2048
            case OUTC * 4096:      conv_w = (const float*)d_in[i]; break;  // 2097152
            case OUTC:             conv_b = (const float*)d_in[i]; break;  // 512
        }
    }

    static int smem_set = 0;
    if (!smem_set) {
        cudaFuncSetAttribute(mma_kernel,
                             cudaFuncAttributeMaxDynamicSharedMemorySize,
                             SM_FLOATS * 4);
        smem_set = 1;
    }

    wsplit_kernel<<<(OUTC * 4096) / 1024, 256>>>(conv_w);
    mma_kernel<<<dim3(2, BQ, KCH), 256, SM_FLOATS * 4>>>(x);
    reduce_kernel<<<RED_BLOCKS + 8, 256>>>(stft_w);
    epilogue_kernel<<<(BQ * OUTC) / BO_PER_BLK, 256>>>(conv_b, (float*)d_out);
}